// round 2
// baseline (speedup 1.0000x reference)
#include <cuda_runtime.h>
#include <cstdint>
#include <cstddef>

#define DIMN   1024
#define HEADS  16
#define HDIM   64
#define BATCH  4
#define SEQ    1024
#define BHN    (BATCH*HEADS)
#define NB     33

#define GM (BATCH*SEQ)
#define GN DIMN
#define GK DIMN

// ---------------- scratch (device globals; no allocation allowed) ----------
__device__ float g_qh[BHN*SEQ*HDIM];
__device__ float g_kh[BHN*SEQ*HDIM];
__device__ float g_vh[BHN*SEQ*HDIM];
__device__ float g_ctx[BATCH*SEQ*DIMN];

// ---------------- tf32 helpers ---------------------------------------------
__device__ __forceinline__ uint32_t f2tf(float x) {
    uint32_t r;
    asm("cvt.rna.tf32.f32 %0, %1;" : "=r"(r) : "f"(x));
    return r;
}

__device__ __forceinline__ void mma_tf32(float* d, const uint32_t* a, const uint32_t* b) {
    asm volatile(
        "mma.sync.aligned.m16n8k8.row.col.f32.tf32.tf32.f32 "
        "{%0,%1,%2,%3},{%4,%5,%6,%7},{%8,%9},{%0,%1,%2,%3};"
        : "+f"(d[0]), "+f"(d[1]), "+f"(d[2]), "+f"(d[3])
        : "r"(a[0]), "r"(a[1]), "r"(a[2]), "r"(a[3]), "r"(b[0]), "r"(b[1]));
}

// ---------------- 3xTF32 GEMM: C = X @ W^T + bias, then *scale --------------
// M=4096, N=1024, K=1024. Block tile 128x128, BK=16, 256 threads (8 warps),
// warp tile 64x32 (4x4 m16n8k8 mma tiles per k8 step).
// head_mode=1: write into [b,h,t,d] head layout; head_mode=0: plain [M,N].
#define SSTR 136   // smem row stride: bank = (8*tig + gid) % 32 -> conflict-free frags

__global__ __launch_bounds__(256)
void sgemm_tc_kernel(const float* __restrict__ X, const float* __restrict__ W,
                     const float* __restrict__ bias, float* __restrict__ out,
                     float scale, int head_mode)
{
    __shared__ float As[16][SSTR];
    __shared__ float Bs[16][SSTR];

    const int tid  = threadIdx.x;
    const int m0   = blockIdx.y * 128;
    const int n0   = blockIdx.x * 128;
    const int warp = tid >> 5;
    const int lane = tid & 31;
    const int gid  = lane >> 2;   // 0..7
    const int tig  = lane & 3;    // 0..3
    const int wm   = warp >> 2;   // 0..1 : 64-row slab
    const int wn   = warp & 3;    // 0..3 : 32-col slab

    float acc[4][4][4];
    #pragma unroll
    for (int i = 0; i < 4; i++)
        #pragma unroll
        for (int j = 0; j < 4; j++)
            #pragma unroll
            for (int e = 0; e < 4; e++) acc[i][j][e] = 0.f;

    for (int k0 = 0; k0 < GK; k0 += 16) {
        __syncthreads();
        // load A/B tiles transposed into smem: As[k][m], Bs[k][n]
        #pragma unroll
        for (int it = 0; it < 2; it++) {
            int idx = tid + it * 256;       // 0..511
            int c4  = idx >> 7;             // 0..3 (k group of 4)
            int r   = idx & 127;            // row within tile
            float4 av = *(const float4*)&X[(size_t)(m0 + r) * GK + k0 + c4 * 4];
            float4 bv = *(const float4*)&W[(size_t)(n0 + r) * GK + k0 + c4 * 4];
            As[c4*4+0][r] = av.x; As[c4*4+1][r] = av.y;
            As[c4*4+2][r] = av.z; As[c4*4+3][r] = av.w;
            Bs[c4*4+0][r] = bv.x; Bs[c4*4+1][r] = bv.y;
            Bs[c4*4+2][r] = bv.z; Bs[c4*4+3][r] = bv.w;
        }
        __syncthreads();

        #pragma unroll
        for (int kk = 0; kk < 16; kk += 8) {
            // B fragments (hi/lo) for 4 n-tiles
            uint32_t bh[4][2], bl[4][2];
            #pragma unroll
            for (int j = 0; j < 4; j++) {
                #pragma unroll
                for (int e = 0; e < 2; e++) {
                    float v = Bs[kk + tig + e*4][wn*32 + j*8 + gid];
                    uint32_t h = f2tf(v);
                    bh[j][e] = h;
                    bl[j][e] = f2tf(v - __uint_as_float(h));
                }
            }
            #pragma unroll
            for (int i = 0; i < 4; i++) {
                int r0 = wm*64 + i*16 + gid;
                float a0 = As[kk + tig    ][r0];
                float a1 = As[kk + tig    ][r0 + 8];
                float a2 = As[kk + tig + 4][r0];
                float a3 = As[kk + tig + 4][r0 + 8];
                uint32_t ah[4], al[4];
                ah[0] = f2tf(a0); al[0] = f2tf(a0 - __uint_as_float(ah[0]));
                ah[1] = f2tf(a1); al[1] = f2tf(a1 - __uint_as_float(ah[1]));
                ah[2] = f2tf(a2); al[2] = f2tf(a2 - __uint_as_float(ah[2]));
                ah[3] = f2tf(a3); al[3] = f2tf(a3 - __uint_as_float(ah[3]));
                #pragma unroll
                for (int j = 0; j < 4; j++) {
                    mma_tf32(acc[i][j], ah, bh[j]);
                    mma_tf32(acc[i][j], al, bh[j]);
                    mma_tf32(acc[i][j], ah, bl[j]);
                }
            }
        }
    }

    // epilogue
    #pragma unroll
    for (int i = 0; i < 4; i++) {
        int r0 = m0 + wm*64 + i*16 + gid;   // rows r0 and r0+8
        #pragma unroll
        for (int j = 0; j < 4; j++) {
            int nc = n0 + wn*32 + j*8 + 2*tig;   // cols nc, nc+1
            float b0 = bias[nc], b1 = bias[nc + 1];
            float v00 = (acc[i][j][0] + b0) * scale;
            float v01 = (acc[i][j][1] + b1) * scale;
            float v10 = (acc[i][j][2] + b0) * scale;
            float v11 = (acc[i][j][3] + b1) * scale;
            if (head_mode) {
                int h = nc >> 6, d = nc & 63;
                int b0i = r0 >> 10, t0 = r0 & (SEQ - 1);
                int r1 = r0 + 8;
                int b1i = r1 >> 10, t1 = r1 & (SEQ - 1);
                float* d0 = out + ((size_t)((b0i*HEADS + h)*SEQ + t0)) * HDIM + d;
                float* d1 = out + ((size_t)((b1i*HEADS + h)*SEQ + t1)) * HDIM + d;
                *(float2*)d0 = make_float2(v00, v01);
                *(float2*)d1 = make_float2(v10, v11);
            } else {
                float* d0 = out + (size_t)r0 * GN + nc;
                float* d1 = out + (size_t)(r0 + 8) * GN + nc;
                *(float2*)d0 = make_float2(v00, v01);
                *(float2*)d1 = make_float2(v10, v11);
            }
        }
    }
}

// ---------------- attention kernel (unchanged from R1, passing) ------------
#define TQ 32
#define TK 128
#define ESTR 1032
#define KSTR 132
#define VSTR 68
#define KVFLOATS 8704
#define SMEM_FLOATS (TQ*ESTR + TQ*HDIM + KVFLOATS + NB*128 + TQ*NB + TQ*NB)
#define SMEM_BYTES  (SMEM_FLOATS * 4)

__global__ __launch_bounds__(256)
void attn_kernel(const float* __restrict__ rpe_w, float* __restrict__ align_out)
{
    extern __shared__ float smem[];
    float* e    = smem;
    float* qs   = e    + TQ * ESTR;
    float* kv   = qs   + TQ * HDIM;
    float* rw   = kv   + KVFLOATS;
    float* proj = rw   + NB * 128;
    float* srow = proj + TQ * NB;

    const int bh  = blockIdx.y;
    const int q0  = blockIdx.x * TQ;
    const int tid = threadIdx.x;

    for (int i = tid; i < NB * 128; i += 256) rw[i] = rpe_w[i];
    const float* qbase = g_qh + ((size_t)bh * SEQ + q0) * HDIM;
    for (int i = tid; i < TQ * HDIM; i += 256) qs[i] = qbase[i];
    __syncthreads();

    for (int i = tid; i < TQ * NB; i += 256) {
        int qi = i / NB, t = i % NB;
        float s = 0.f;
        #pragma unroll
        for (int d = 0; d < HDIM; d++) s += qs[qi*HDIM + d] * rw[t*128 + d];
        proj[i] = s;
    }
    __syncthreads();

    const int qg = tid >> 5;
    const int kg = tid & 31;
    for (int kt = 0; kt < SEQ; kt += TK) {
        const float* kbase = g_kh + ((size_t)bh * SEQ + kt) * HDIM;
        for (int i = tid * 4; i < TK * HDIM; i += 1024) {
            float4 v = *(const float4*)&kbase[i];
            int r = i / HDIM, c = i % HDIM;
            kv[(c+0)*KSTR + r] = v.x;
            kv[(c+1)*KSTR + r] = v.y;
            kv[(c+2)*KSTR + r] = v.z;
            kv[(c+3)*KSTR + r] = v.w;
        }
        __syncthreads();

        float acc[4][4];
        #pragma unroll
        for (int i = 0; i < 4; i++)
            #pragma unroll
            for (int j = 0; j < 4; j++) acc[i][j] = 0.f;

        #pragma unroll 8
        for (int d = 0; d < HDIM; d++) {
            float a0 = qs[(qg*4+0)*HDIM + d];
            float a1 = qs[(qg*4+1)*HDIM + d];
            float a2 = qs[(qg*4+2)*HDIM + d];
            float a3 = qs[(qg*4+3)*HDIM + d];
            float4 bv = *(float4*)&kv[d*KSTR + kg*4];
            acc[0][0] += a0*bv.x; acc[0][1] += a0*bv.y; acc[0][2] += a0*bv.z; acc[0][3] += a0*bv.w;
            acc[1][0] += a1*bv.x; acc[1][1] += a1*bv.y; acc[1][2] += a1*bv.z; acc[1][3] += a1*bv.w;
            acc[2][0] += a2*bv.x; acc[2][1] += a2*bv.y; acc[2][2] += a2*bv.z; acc[2][3] += a2*bv.w;
            acc[3][0] += a3*bv.x; acc[3][1] += a3*bv.y; acc[3][2] += a3*bv.z; acc[3][3] += a3*bv.w;
        }

        #pragma unroll
        for (int i = 0; i < 4; i++) {
            int q = qg*4 + i;
            int qglob = q0 + q;
            #pragma unroll
            for (int j = 0; j < 4; j++) {
                int k = kt + kg*4 + j;
                int dd = qglob - k;
                dd = dd < -16 ? -16 : (dd > 16 ? 16 : dd);
                e[q*ESTR + k] = acc[i][j] + proj[q*NB + dd + 16];
            }
        }
        __syncthreads();
    }

    const int warp = tid >> 5, lane = tid & 31;
    for (int q = warp*4; q < warp*4 + 4; q++) {
        int qglob = q0 + q;
        float* row = e + q*ESTR;
        float mx = -1e30f;
        for (int k = lane; k < SEQ; k += 32) mx = fmaxf(mx, row[k]);
        #pragma unroll
        for (int o = 16; o; o >>= 1) mx = fmaxf(mx, __shfl_xor_sync(0xffffffffu, mx, o));
        float sum = 0.f;
        for (int k = lane; k < SEQ; k += 32) {
            float p = __expf(row[k] - mx);
            row[k] = p; sum += p;
        }
        #pragma unroll
        for (int o = 16; o; o >>= 1) sum += __shfl_xor_sync(0xffffffffu, sum, o);
        float inv = 1.f / sum;
        float slo = 0.f, shi = 0.f;
        float* arow = align_out + ((size_t)(bh * SEQ + qglob)) * SEQ;
        for (int k = lane; k < SEQ; k += 32) {
            float p = row[k] * inv;
            row[k] = p;
            arow[k] = p;
            if (k <= qglob - 16) slo += p;
            if (k >= qglob + 16) shi += p;
        }
        #pragma unroll
        for (int o = 16; o; o >>= 1) {
            slo += __shfl_xor_sync(0xffffffffu, slo, o);
            shi += __shfl_xor_sync(0xffffffffu, shi, o);
        }
        if (lane == 0) { srow[q*NB + 32] = slo; srow[q*NB + 0] = shi; }
        if (lane >= 1 && lane <= 31) {
            int k = qglob + 16 - lane;
            srow[q*NB + lane] = (k >= 0 && k < SEQ) ? row[k] : 0.f;
        }
    }
    __syncthreads();

    const int cq = tid >> 3;
    const int dg = tid & 7;
    float cacc[8];
    #pragma unroll
    for (int i = 0; i < 8; i++) cacc[i] = 0.f;

    for (int kt = 0; kt < SEQ; kt += TK) {
        const float* vbase = g_vh + ((size_t)bh * SEQ + kt) * HDIM;
        for (int i = tid * 4; i < TK * HDIM; i += 1024) {
            float4 v = *(const float4*)&vbase[i];
            int r = i / HDIM, c = i % HDIM;
            *(float4*)&kv[r*VSTR + c] = v;
        }
        __syncthreads();
        #pragma unroll 4
        for (int k = 0; k < TK; k++) {
            float p = e[cq*ESTR + kt + k];
            float4 v0 = *(float4*)&kv[k*VSTR + dg*8];
            float4 v1 = *(float4*)&kv[k*VSTR + dg*8 + 4];
            cacc[0] += p*v0.x; cacc[1] += p*v0.y; cacc[2] += p*v0.z; cacc[3] += p*v0.w;
            cacc[4] += p*v1.x; cacc[5] += p*v1.y; cacc[6] += p*v1.z; cacc[7] += p*v1.w;
        }
        __syncthreads();
    }

    #pragma unroll
    for (int t = 0; t < NB; t++) {
        float s = srow[cq*NB + t];
        const float* rv = &rw[t*128 + 64 + dg*8];
        #pragma unroll
        for (int i = 0; i < 8; i++) cacc[i] += s * rv[i];
    }

    int b = bh / HEADS, h = bh % HEADS;
    float* dst = g_ctx + ((size_t)(b*SEQ + q0 + cq)) * DIMN + h*HDIM + dg*8;
    *(float4*)dst       = make_float4(cacc[0], cacc[1], cacc[2], cacc[3]);
    *(float4*)(dst + 4) = make_float4(cacc[4], cacc[5], cacc[6], cacc[7]);
}

// ---------------- launch ---------------------------------------------------
extern "C" void kernel_launch(void* const* d_in, const int* in_sizes, int n_in,
                              void* d_out, int out_size)
{
    const float* q     = (const float*)d_in[0];
    const float* k     = (const float*)d_in[1];
    const float* v     = (const float*)d_in[2];
    const float* Wq    = (const float*)d_in[3];
    const float* bq    = (const float*)d_in[4];
    const float* Wk    = (const float*)d_in[5];
    const float* bk    = (const float*)d_in[6];
    const float* Wv    = (const float*)d_in[7];
    const float* bv    = (const float*)d_in[8];
    const float* rpe_w = (const float*)d_in[9];
    const float* Wo    = (const float*)d_in[10];
    const float* bo    = (const float*)d_in[11];
    float* outp = (float*)d_out;

    float *qh, *kh, *vh, *ctx;
    cudaGetSymbolAddress((void**)&qh,  g_qh);
    cudaGetSymbolAddress((void**)&kh,  g_kh);
    cudaGetSymbolAddress((void**)&vh,  g_vh);
    cudaGetSymbolAddress((void**)&ctx, g_ctx);

    cudaFuncSetAttribute(attn_kernel, cudaFuncAttributeMaxDynamicSharedMemorySize, SMEM_BYTES);

    dim3 gg(GN/128, GM/128);
    sgemm_tc_kernel<<<gg, 256>>>(q, Wq, bq, qh, 0.125f, 1);   // 1/sqrt(64) baked in
    sgemm_tc_kernel<<<gg, 256>>>(k, Wk, bk, kh, 1.0f, 1);
    sgemm_tc_kernel<<<gg, 256>>>(v, Wv, bv, vh, 1.0f, 1);

    float* align_out = outp + (size_t)BATCH * SEQ * DIMN;
    attn_kernel<<<dim3(SEQ/TQ, BHN), 256, SMEM_BYTES>>>(rpe_w, align_out);

    sgemm_tc_kernel<<<gg, 256>>>(ctx, Wo, bo, outp, 1.0f, 0);
}

// round 3
// speedup vs baseline: 1.3520x; 1.3520x over previous
#include <cuda_runtime.h>
#include <cstdint>
#include <cstddef>

#define DIMN   1024
#define HEADS  16
#define HDIM   64
#define BATCH  4
#define SEQ    1024
#define BHN    (BATCH*HEADS)
#define NB     33

#define GM (BATCH*SEQ)
#define GN DIMN
#define GK DIMN

// ---------------- scratch (device globals; no allocation allowed) ----------
__device__ float g_qh[BHN*SEQ*HDIM];
__device__ float g_kh[BHN*SEQ*HDIM];
__device__ float g_vh[BHN*SEQ*HDIM];
__device__ float g_ctx[BATCH*SEQ*DIMN];

// ---------------- helpers ---------------------------------------------------
__device__ __forceinline__ float tf32r(float x) {   // RNA-round to tf32, as float
    uint32_t r;
    asm("cvt.rna.tf32.f32 %0, %1;" : "=r"(r) : "f"(x));
    return __uint_as_float(r);
}

__device__ __forceinline__ void mma8(float* d, const float* a, const float* b) {
    asm volatile(
        "mma.sync.aligned.m16n8k8.row.col.f32.tf32.tf32.f32 "
        "{%0,%1,%2,%3},{%4,%5,%6,%7},{%8,%9},{%0,%1,%2,%3};"
        : "+f"(d[0]), "+f"(d[1]), "+f"(d[2]), "+f"(d[3])
        : "r"(__float_as_uint(a[0])), "r"(__float_as_uint(a[1])),
          "r"(__float_as_uint(a[2])), "r"(__float_as_uint(a[3])),
          "r"(__float_as_uint(b[0])), "r"(__float_as_uint(b[1])));
}

__device__ __forceinline__ uint32_t smem_u32(const void* p) {
    uint32_t r;
    asm("{ .reg .u64 t; cvta.to.shared.u64 t, %1; cvt.u32.u64 %0, t; }" : "=r"(r) : "l"(p));
    return r;
}

#define CP16(dst_u32, src_ptr) \
    asm volatile("cp.async.cg.shared.global [%0], [%1], 16;" :: "r"(dst_u32), "l"(src_ptr))
#define CP_COMMIT() asm volatile("cp.async.commit_group;")
#define CP_WAIT1()  asm volatile("cp.async.wait_group 1;")
#define CP_WAIT0()  asm volatile("cp.async.wait_group 0;")

// ---------------- 3xTF32 GEMM, cp.async double-buffered --------------------
// C = X @ W^T + bias, *scale.  M=4096,N=1024,K=1024. 128x128 tile, BK=16.
#define BSTR 28                       // row stride (floats): 112B, 16B-aligned, conflict-free
#define GEMM_SMEM_FLOATS (4*128*BSTR) // 2 stages x (A+B)
#define GEMM_SMEM_BYTES  (GEMM_SMEM_FLOATS*4)

__global__ __launch_bounds__(256, 2)
void sgemm_tc_kernel(const float* __restrict__ X, const float* __restrict__ W,
                     const float* __restrict__ bias, float* __restrict__ out,
                     float scale, int head_mode)
{
    extern __shared__ float sm[];
    float* As = sm;                    // [2][128*BSTR]
    float* Bs = sm + 2*128*BSTR;

    const int tid  = threadIdx.x;
    const int m0   = blockIdx.y * 128;
    const int n0   = blockIdx.x * 128;
    const int warp = tid >> 5;
    const int lane = tid & 31;
    const int gid  = lane >> 2;
    const int tig  = lane & 3;
    const int wm   = warp >> 2;
    const int wn   = warp & 3;

    const uint32_t aU = smem_u32(As);
    const uint32_t bU = smem_u32(Bs);

    float acc[4][4][4];
    #pragma unroll
    for (int i = 0; i < 4; i++)
        #pragma unroll
        for (int j = 0; j < 4; j++)
            #pragma unroll
            for (int e = 0; e < 4; e++) acc[i][j][e] = 0.f;

    // prefetch stage 0
    {
        #pragma unroll
        for (int it = 0; it < 2; it++) {
            int id = tid + it*256;
            int r = id >> 2, c = (id & 3) * 4;
            CP16(aU + (r*BSTR + c)*4, X + (size_t)(m0 + r)*GK + c);
            CP16(bU + (r*BSTR + c)*4, W + (size_t)(n0 + r)*GK + c);
        }
        CP_COMMIT();
    }

    for (int t = 0; t < 64; t++) {
        if (t < 63) {
            int buf = (t + 1) & 1, k0 = (t + 1) * 16;
            #pragma unroll
            for (int it = 0; it < 2; it++) {
                int id = tid + it*256;
                int r = id >> 2, c = (id & 3) * 4;
                CP16(aU + (buf*128*BSTR + r*BSTR + c)*4, X + (size_t)(m0 + r)*GK + k0 + c);
                CP16(bU + (buf*128*BSTR + r*BSTR + c)*4, W + (size_t)(n0 + r)*GK + k0 + c);
            }
            CP_COMMIT();
            CP_WAIT1();
        } else {
            CP_WAIT0();
        }
        __syncthreads();

        const float* A = As + (t & 1)*128*BSTR;
        const float* B = Bs + (t & 1)*128*BSTR;
        #pragma unroll
        for (int kk = 0; kk < 16; kk += 8) {
            float bh[4][2], bl[4][2];
            #pragma unroll
            for (int j = 0; j < 4; j++) {
                int nb = (wn*32 + j*8 + gid)*BSTR + kk + tig;
                float v0 = B[nb], v1 = B[nb + 4];
                bh[j][0] = tf32r(v0); bl[j][0] = v0 - bh[j][0];
                bh[j][1] = tf32r(v1); bl[j][1] = v1 - bh[j][1];
            }
            #pragma unroll
            for (int i = 0; i < 4; i++) {
                int rb = (wm*64 + i*16 + gid)*BSTR + kk + tig;
                float a0 = A[rb], a1 = A[rb + 8*BSTR], a2 = A[rb + 4], a3 = A[rb + 8*BSTR + 4];
                float ah[4], al[4];
                ah[0] = tf32r(a0); al[0] = a0 - ah[0];
                ah[1] = tf32r(a1); al[1] = a1 - ah[1];
                ah[2] = tf32r(a2); al[2] = a2 - ah[2];
                ah[3] = tf32r(a3); al[3] = a3 - ah[3];
                #pragma unroll
                for (int j = 0; j < 4; j++) {
                    mma8(acc[i][j], ah, bh[j]);
                    mma8(acc[i][j], al, bh[j]);
                    mma8(acc[i][j], ah, bl[j]);
                }
            }
        }
        __syncthreads();
    }

    // epilogue (same mapping as R2, which verified correct)
    #pragma unroll
    for (int i = 0; i < 4; i++) {
        int r0 = m0 + wm*64 + i*16 + gid;
        #pragma unroll
        for (int j = 0; j < 4; j++) {
            int nc = n0 + wn*32 + j*8 + 2*tig;
            float b0 = bias[nc], b1 = bias[nc + 1];
            float v00 = (acc[i][j][0] + b0) * scale;
            float v01 = (acc[i][j][1] + b1) * scale;
            float v10 = (acc[i][j][2] + b0) * scale;
            float v11 = (acc[i][j][3] + b1) * scale;
            if (head_mode) {
                int h = nc >> 6, d = nc & 63;
                int b0i = r0 >> 10, t0 = r0 & (SEQ - 1);
                int r1 = r0 + 8;
                int b1i = r1 >> 10, t1 = r1 & (SEQ - 1);
                float* d0 = out + ((size_t)((b0i*HEADS + h)*SEQ + t0)) * HDIM + d;
                float* d1 = out + ((size_t)((b1i*HEADS + h)*SEQ + t1)) * HDIM + d;
                *(float2*)d0 = make_float2(v00, v01);
                *(float2*)d1 = make_float2(v10, v11);
            } else {
                float* d0 = out + (size_t)r0 * GN + nc;
                float* d1 = out + (size_t)(r0 + 8) * GN + nc;
                *(float2*)d0 = make_float2(v00, v01);
                *(float2*)d1 = make_float2(v10, v11);
            }
        }
    }
}

// ---------------- attention kernel: tensor-core S and PV -------------------
#define TQ   32
#define ESTR 1032          // e stride: %32==8 -> conflict-free frag reads
#define QSTR 72            // q/kv tile stride: %32==8, 16B-aligned rows
// smem float offsets
#define OFF_E    0
#define OFF_QHI  (TQ*ESTR)                  // 33024
#define OFF_QLO  (OFF_QHI + TQ*QSTR)        // +2304
#define OFF_KV   (OFF_QLO + TQ*QSTR)        // +2304
#define OFF_RWV  (OFF_KV  + 128*QSTR)       // +9216
#define OFF_PROJ (OFF_RWV + NB*64)          // +2112
#define OFF_SROW (OFF_PROJ + TQ*NB)         // +1056
#define ATT_SMEM_FLOATS (OFF_SROW + TQ*NB)  // +1056 = 51072
#define ATT_SMEM_BYTES  (ATT_SMEM_FLOATS*4) // 204288

__device__ __forceinline__ int rpe_clip(int dd) {
    dd = dd < -16 ? -16 : (dd > 16 ? 16 : dd);
    return dd + 16;
}

__global__ __launch_bounds__(512)
void attn_kernel(const float* __restrict__ rpe_w, float* __restrict__ align_out)
{
    extern __shared__ float sm[];
    float* e    = sm + OFF_E;
    float* qhi  = sm + OFF_QHI;
    float* qlo  = sm + OFF_QLO;
    float* kv   = sm + OFF_KV;
    float* rwv  = sm + OFF_RWV;
    float* proj = sm + OFF_PROJ;
    float* srow = sm + OFF_SROW;

    const int bhid = blockIdx.y;
    const int q0   = blockIdx.x * TQ;
    const int tid  = threadIdx.x;
    const int warp = tid >> 5, lane = tid & 31;
    const int gid  = lane >> 2, tig = lane & 3;

    // ---- prologue: Q tile hi/lo, rpe_v table ----
    const float* qbase = g_qh + ((size_t)bhid * SEQ + q0) * HDIM;
    {
        int r = tid >> 4, c4 = (tid & 15) << 2;              // 512 threads = 512 float4
        float4 v = *(const float4*)&qbase[r*64 + c4];
        float h;
        h = tf32r(v.x); qhi[r*QSTR + c4 + 0] = h; qlo[r*QSTR + c4 + 0] = v.x - h;
        h = tf32r(v.y); qhi[r*QSTR + c4 + 1] = h; qlo[r*QSTR + c4 + 1] = v.y - h;
        h = tf32r(v.z); qhi[r*QSTR + c4 + 2] = h; qlo[r*QSTR + c4 + 2] = v.z - h;
        h = tf32r(v.w); qhi[r*QSTR + c4 + 3] = h; qlo[r*QSTR + c4 + 3] = v.w - h;
    }
    for (int i = tid; i < NB*64; i += 512) {
        int t = i >> 6, d = i & 63;
        rwv[i] = rpe_w[t*128 + 64 + d];
    }
    __syncthreads();

    // proj[q][t] = qh[q] . rpe_w[t, 0:64]
    for (int i = tid; i < TQ*NB; i += 512) {
        int q = i / NB, t = i - q*NB;
        const float* rp = rpe_w + t*128;
        float s = 0.f;
        #pragma unroll 16
        for (int d = 0; d < 64; d++) s += (qhi[q*QSTR + d] + qlo[q*QSTR + d]) * __ldg(&rp[d]);
        proj[i] = s;
    }
    __syncthreads();

    // ---- S = Q K^T (3xTF32 mma) + rpe_q, into e ----
    const int mS = warp & 1;         // m-tile (16 rows)
    const int np = warp >> 1;        // n-pair 0..7 (2 n-tiles of 8 within the 128-wide kt tile)
    for (int kt = 0; kt < SEQ; kt += 128) {
        __syncthreads();
        const float* kb = g_kh + ((size_t)bhid * SEQ + kt) * HDIM;
        for (int i = tid; i < 2048; i += 512) {
            int r = i >> 4, c4 = (i & 15) << 2;
            *(float4*)&kv[r*QSTR + c4] = *(const float4*)&kb[r*64 + c4];
        }
        __syncthreads();

        float acc[2][4] = {{0.f,0.f,0.f,0.f},{0.f,0.f,0.f,0.f}};
        #pragma unroll
        for (int kk = 0; kk < 64; kk += 8) {
            int ab = (mS*16 + gid)*QSTR + kk + tig;
            float ah[4] = { qhi[ab], qhi[ab + 8*QSTR], qhi[ab + 4], qhi[ab + 8*QSTR + 4] };
            float al[4] = { qlo[ab], qlo[ab + 8*QSTR], qlo[ab + 4], qlo[ab + 8*QSTR + 4] };
            #pragma unroll
            for (int jj = 0; jj < 2; jj++) {
                int nb = ((np*2 + jj)*8 + gid)*QSTR + kk + tig;
                float b0 = kv[nb], b1 = kv[nb + 4];
                float bh[2], bl[2];
                bh[0] = tf32r(b0); bl[0] = b0 - bh[0];
                bh[1] = tf32r(b1); bl[1] = b1 - bh[1];
                mma8(acc[jj], ah, bh);
                mma8(acc[jj], al, bh);
                mma8(acc[jj], ah, bl);
            }
        }
        // scatter with rpe_q add
        int qA = mS*16 + gid, qB = qA + 8;
        int qgA = q0 + qA, qgB = q0 + qB;
        #pragma unroll
        for (int jj = 0; jj < 2; jj++) {
            int k0c = kt + (np*2 + jj)*8 + 2*tig;
            e[qA*ESTR + k0c    ] = acc[jj][0] + proj[qA*NB + rpe_clip(qgA - k0c)];
            e[qA*ESTR + k0c + 1] = acc[jj][1] + proj[qA*NB + rpe_clip(qgA - k0c - 1)];
            e[qB*ESTR + k0c    ] = acc[jj][2] + proj[qB*NB + rpe_clip(qgB - k0c)];
            e[qB*ESTR + k0c + 1] = acc[jj][3] + proj[qB*NB + rpe_clip(qgB - k0c - 1)];
        }
    }
    __syncthreads();

    // ---- softmax rows + alignment output + RPE bucket sums (16 warps x 2 rows) ----
    for (int q = warp*2; q < warp*2 + 2; q++) {
        int qglob = q0 + q;
        float* row = e + q*ESTR;
        float mx = -1e30f;
        for (int k = lane; k < SEQ; k += 32) mx = fmaxf(mx, row[k]);
        #pragma unroll
        for (int o = 16; o; o >>= 1) mx = fmaxf(mx, __shfl_xor_sync(0xffffffffu, mx, o));
        float sum = 0.f;
        for (int k = lane; k < SEQ; k += 32) {
            float p = __expf(row[k] - mx);
            row[k] = p; sum += p;
        }
        #pragma unroll
        for (int o = 16; o; o >>= 1) sum += __shfl_xor_sync(0xffffffffu, sum, o);
        float inv = 1.f / sum;
        float slo = 0.f, shi = 0.f;
        float* arow = align_out + ((size_t)(bhid * SEQ + qglob)) * SEQ;
        for (int k = lane; k < SEQ; k += 32) {
            float p = row[k] * inv;
            row[k] = p;
            arow[k] = p;
            if (k <= qglob - 16) slo += p;
            if (k >= qglob + 16) shi += p;
        }
        #pragma unroll
        for (int o = 16; o; o >>= 1) {
            slo += __shfl_xor_sync(0xffffffffu, slo, o);
            shi += __shfl_xor_sync(0xffffffffu, shi, o);
        }
        if (lane == 0) { srow[q*NB + 32] = slo; srow[q*NB + 0] = shi; }
        if (lane >= 1) {
            int k = qglob + 16 - lane;
            srow[q*NB + lane] = (k >= 0 && k < SEQ) ? row[k] : 0.f;
        }
    }
    __syncthreads();

    // ---- rpecv[32][64] = srow @ rpe_v  (reuse qhi buffer) ----
    for (int i = tid; i < TQ*64; i += 512) {
        int q = i >> 6, d = i & 63;
        float s = 0.f;
        #pragma unroll
        for (int t = 0; t < NB; t++) s += srow[q*NB + t] * rwv[t*64 + d];
        qhi[i] = s;
    }

    // ---- PV (3xTF32 mma), acc across all kt ----
    const int mP = warp & 1;
    const int nt = warp >> 1;       // 0..7 n-tile over HDIM=64
    float accP[4] = {0.f, 0.f, 0.f, 0.f};
    for (int kt = 0; kt < SEQ; kt += 128) {
        __syncthreads();
        const float* vb = g_vh + ((size_t)bhid * SEQ + kt) * HDIM;
        for (int i = tid; i < 2048; i += 512) {
            int r = i >> 4, c4 = (i & 15) << 2;
            *(float4*)&kv[r*QSTR + c4] = *(const float4*)&vb[r*64 + c4];
        }
        __syncthreads();
        #pragma unroll 4
        for (int kk = 0; kk < 128; kk += 8) {
            int eb = (mP*16 + gid)*ESTR + kt + kk + tig;
            float a0 = e[eb], a1 = e[eb + 8*ESTR], a2 = e[eb + 4], a3 = e[eb + 8*ESTR + 4];
            float ah[4], al[4];
            ah[0] = tf32r(a0); al[0] = a0 - ah[0];
            ah[1] = tf32r(a1); al[1] = a1 - ah[1];
            ah[2] = tf32r(a2); al[2] = a2 - ah[2];
            ah[3] = tf32r(a3); al[3] = a3 - ah[3];
            int vb0 = (kk + tig)*QSTR + nt*8 + gid;
            float b0 = kv[vb0], b1 = kv[vb0 + 4*QSTR];
            float bh[2], bl[2];
            bh[0] = tf32r(b0); bl[0] = b0 - bh[0];
            bh[1] = tf32r(b1); bl[1] = b1 - bh[1];
            mma8(accP, ah, bh);
            mma8(accP, al, bh);
            mma8(accP, ah, bl);
        }
    }

    // ---- epilogue: + rpecv, write g_ctx ----
    {
        int qA = mP*16 + gid, qB = qA + 8;
        int d0 = nt*8 + 2*tig;
        int b = bhid / HEADS, h = bhid % HEADS;
        float v00 = accP[0] + qhi[qA*64 + d0];
        float v01 = accP[1] + qhi[qA*64 + d0 + 1];
        float v10 = accP[2] + qhi[qB*64 + d0];
        float v11 = accP[3] + qhi[qB*64 + d0 + 1];
        float* dst0 = g_ctx + ((size_t)(b*SEQ + q0 + qA)) * DIMN + h*64 + d0;
        float* dst1 = g_ctx + ((size_t)(b*SEQ + q0 + qB)) * DIMN + h*64 + d0;
        *(float2*)dst0 = make_float2(v00, v01);
        *(float2*)dst1 = make_float2(v10, v11);
    }
}

// ---------------- launch ---------------------------------------------------
extern "C" void kernel_launch(void* const* d_in, const int* in_sizes, int n_in,
                              void* d_out, int out_size)
{
    const float* q     = (const float*)d_in[0];
    const float* k     = (const float*)d_in[1];
    const float* v     = (const float*)d_in[2];
    const float* Wq    = (const float*)d_in[3];
    const float* bq    = (const float*)d_in[4];
    const float* Wk    = (const float*)d_in[5];
    const float* bk    = (const float*)d_in[6];
    const float* Wv    = (const float*)d_in[7];
    const float* bv    = (const float*)d_in[8];
    const float* rpe_w = (const float*)d_in[9];
    const float* Wo    = (const float*)d_in[10];
    const float* bo    = (const float*)d_in[11];
    float* outp = (float*)d_out;

    float *qh, *kh, *vh, *ctx;
    cudaGetSymbolAddress((void**)&qh,  g_qh);
    cudaGetSymbolAddress((void**)&kh,  g_kh);
    cudaGetSymbolAddress((void**)&vh,  g_vh);
    cudaGetSymbolAddress((void**)&ctx, g_ctx);

    static int inited = 0;
    if (!inited) {
        cudaFuncSetAttribute(sgemm_tc_kernel, cudaFuncAttributeMaxDynamicSharedMemorySize, GEMM_SMEM_BYTES);
        cudaFuncSetAttribute(attn_kernel,     cudaFuncAttributeMaxDynamicSharedMemorySize, ATT_SMEM_BYTES);
        inited = 1;
    }

    dim3 gg(GN/128, GM/128);
    sgemm_tc_kernel<<<gg, 256, GEMM_SMEM_BYTES>>>(q, Wq, bq, qh, 0.125f, 1);
    sgemm_tc_kernel<<<gg, 256, GEMM_SMEM_BYTES>>>(k, Wk, bk, kh, 1.0f, 1);
    sgemm_tc_kernel<<<gg, 256, GEMM_SMEM_BYTES>>>(v, Wv, bv, vh, 1.0f, 1);

    float* align_out = outp + (size_t)BATCH * SEQ * DIMN;
    attn_kernel<<<dim3(SEQ/TQ, BHN), 512, ATT_SMEM_BYTES>>>(rpe_w, align_out);

    sgemm_tc_kernel<<<gg, 256, GEMM_SMEM_BYTES>>>(ctx, Wo, bo, outp, 1.0f, 0);
}

// round 5
// speedup vs baseline: 1.9363x; 1.4322x over previous
#include <cuda_runtime.h>
#include <cuda_bf16.h>
#include <cstdint>
#include <cstddef>

#define DIMN   1024
#define HEADS  16
#define HDIM   64
#define BATCH  4
#define SEQ    1024
#define BHN    (BATCH*HEADS)
#define NB     33

#define GM (BATCH*SEQ)
#define GN DIMN
#define GK DIMN

typedef __nv_bfloat16 bf16;

// ---------------- scratch (device globals; no allocation allowed) ----------
__device__ bf16 g_xhi[GM*GK];
__device__ bf16 g_xlo[GM*GK];
__device__ bf16 g_whi[GN*GK];
__device__ bf16 g_wlo[GN*GK];
__device__ bf16 g_qhh[BHN*SEQ*HDIM];
__device__ bf16 g_qhl[BHN*SEQ*HDIM];
__device__ bf16 g_khh[BHN*SEQ*HDIM];
__device__ bf16 g_khl[BHN*SEQ*HDIM];
__device__ bf16 g_vhh[BHN*SEQ*HDIM];
__device__ bf16 g_vhl[BHN*SEQ*HDIM];
__device__ bf16 g_vth[BHN*HDIM*SEQ];
__device__ bf16 g_vtl[BHN*HDIM*SEQ];

// ---------------- helpers ---------------------------------------------------
__device__ __forceinline__ void mma16(float* d, const uint32_t* a, const uint32_t* b) {
    asm volatile(
        "mma.sync.aligned.m16n8k16.row.col.f32.bf16.bf16.f32 "
        "{%0,%1,%2,%3},{%4,%5,%6,%7},{%8,%9},{%0,%1,%2,%3};"
        : "+f"(d[0]), "+f"(d[1]), "+f"(d[2]), "+f"(d[3])
        : "r"(a[0]), "r"(a[1]), "r"(a[2]), "r"(a[3]), "r"(b[0]), "r"(b[1]));
}
__device__ __forceinline__ uint32_t smem_u32(const void* p) {
    uint32_t r;
    asm("{ .reg .u64 t; cvta.to.shared.u64 t, %1; cvt.u32.u64 %0, t; }" : "=r"(r) : "l"(p));
    return r;
}
__device__ __forceinline__ uint32_t pack2(float x, float y) {
    uint32_t r;
    bf16 a = __float2bfloat16_rn(x), b = __float2bfloat16_rn(y);
    asm("mov.b32 %0, {%1, %2};" : "=r"(r) : "h"(*(uint16_t*)&a), "h"(*(uint16_t*)&b));
    return r;
}
#define CP16(dst_u32, src_ptr) \
    asm volatile("cp.async.cg.shared.global [%0], [%1], 16;" :: "r"(dst_u32), "l"(src_ptr))
#define CP_COMMIT() asm volatile("cp.async.commit_group;")
#define CP_WAIT1()  asm volatile("cp.async.wait_group 1;")
#define CP_WAIT0()  asm volatile("cp.async.wait_group 0;")

// ---------------- split fp32 -> bf16 hi/lo ----------------------------------
__global__ __launch_bounds__(256)
void split_bf16_kernel(const float* __restrict__ src,
                       bf16* __restrict__ hi, bf16* __restrict__ lo, int n4)
{
    int i = blockIdx.x * 256 + threadIdx.x;
    if (i >= n4) return;
    float4 v = ((const float4*)src)[i];
    float f[4] = {v.x, v.y, v.z, v.w};
    bf16 h[4], l[4];
    #pragma unroll
    for (int j = 0; j < 4; j++) {
        h[j] = __float2bfloat16_rn(f[j]);
        l[j] = __float2bfloat16_rn(f[j] - __bfloat162float(h[j]));
    }
    *(uint2*)&hi[(size_t)i*4] = *(uint2*)h;
    *(uint2*)&lo[(size_t)i*4] = *(uint2*)l;
}

// ---------------- V transpose: [bh][t][d] -> [bh][d][t] ---------------------
__global__ __launch_bounds__(256)
void vtrans_kernel(const bf16* __restrict__ ih, const bf16* __restrict__ il,
                   bf16* __restrict__ oh, bf16* __restrict__ ol)
{
    __shared__ bf16 th[64*136], tl[64*136];
    const int bh = blockIdx.y, t0 = blockIdx.x * 128, tid = threadIdx.x;
    #pragma unroll
    for (int it = 0; it < 4; it++) {
        int idx = tid + it*256;           // 0..1023
        int r = idx >> 3, c8 = idx & 7;
        bf16 a[8];
        *(uint4*)a = *(const uint4*)&ih[((size_t)bh*1024 + t0 + r)*64 + c8*8];
        #pragma unroll
        for (int j = 0; j < 8; j++) th[(c8*8 + j)*136 + r] = a[j];
        *(uint4*)a = *(const uint4*)&il[((size_t)bh*1024 + t0 + r)*64 + c8*8];
        #pragma unroll
        for (int j = 0; j < 8; j++) tl[(c8*8 + j)*136 + r] = a[j];
    }
    __syncthreads();
    #pragma unroll
    for (int it = 0; it < 4; it++) {
        int idx = tid + it*256;
        int d = idx >> 4, tc = idx & 15;
        bf16 a[8];
        #pragma unroll
        for (int j = 0; j < 8; j++) a[j] = th[d*136 + tc*8 + j];
        *(uint4*)&oh[((size_t)bh*64 + d)*1024 + t0 + tc*8] = *(uint4*)a;
        #pragma unroll
        for (int j = 0; j < 8; j++) a[j] = tl[d*136 + tc*8 + j];
        *(uint4*)&ol[((size_t)bh*64 + d)*1024 + t0 + tc*8] = *(uint4*)a;
    }
}

// ---------------- bf16x3 GEMM: C = X @ W^T + bias, *scale -------------------
// M=4096,N=1024,K=1024. 128x128 tile, BK=32, cp.async double-buffered.
// mode 0: fp32 out[M][N].  mode 1: bf16 hi/lo out in [bh][t][d] head layout.
#define KS    40                   // bf16 row stride (80B): conflict-free frags
#define TILEB (128*KS*2)           // 10240 B per tile
#define STAGEB (4*TILEB)           // Ah,Al,Bh,Bl
#define GEMM_SMEM_BYTES (2*STAGEB) // 81920

__global__ __launch_bounds__(256, 2)
void gemm_bf16_kernel(const bf16* __restrict__ Xh, const bf16* __restrict__ Xl,
                      const bf16* __restrict__ Wh, const bf16* __restrict__ Wl,
                      const float* __restrict__ bias, float* __restrict__ outf,
                      bf16* __restrict__ oh, bf16* __restrict__ ol,
                      float scale, int mode)
{
    extern __shared__ char gsm[];
    const uint32_t sb = smem_u32(gsm);
    const int tid  = threadIdx.x;
    const int m0   = blockIdx.y * 128;
    const int n0   = blockIdx.x * 128;
    const int warp = tid >> 5, lane = tid & 31;
    const int gid  = lane >> 2, tig = lane & 3;
    const int wm   = warp >> 2, wn = warp & 3;

    const bf16* srcs[4] = { Xh, Xl, Wh, Wl };

    float acc[4][4][4];
    #pragma unroll
    for (int i = 0; i < 4; i++)
        #pragma unroll
        for (int j = 0; j < 4; j++)
            #pragma unroll
            for (int e = 0; e < 4; e++) acc[i][j][e] = 0.f;

    auto fill = [&](int s) {
        const int k0 = s * 32;
        const uint32_t bU = sb + (uint32_t)(s & 1) * STAGEB;
        #pragma unroll
        for (int t = 0; t < 4; t++) {
            const bf16* src = srcs[t];
            const int r0 = (t < 2) ? m0 : n0;
            #pragma unroll
            for (int it = 0; it < 2; it++) {
                int idx = tid + it * 256;
                int r = idx >> 2, c = idx & 3;
                CP16(bU + t*TILEB + (uint32_t)(r*80 + c*16),
                     src + (size_t)(r0 + r) * GK + k0 + c*8);
            }
        }
        CP_COMMIT();
    };

    fill(0);
    fill(1);
    for (int t = 0; t < 32; t++) {
        if (t < 31) CP_WAIT1(); else CP_WAIT0();
        __syncthreads();

        const uint32_t* Ah = (const uint32_t*)(gsm + (size_t)(t & 1)*STAGEB);
        const uint32_t* Al = Ah + TILEB/4;
        const uint32_t* Bh = Ah + 2*(TILEB/4);
        const uint32_t* Bl = Ah + 3*(TILEB/4);

        #pragma unroll
        for (int kk = 0; kk < 32; kk += 16) {
            const int kw = kk >> 1;
            uint32_t bhf[4][2], blf[4][2];
            #pragma unroll
            for (int j = 0; j < 4; j++) {
                int wx = (wn*32 + j*8 + gid)*20 + kw + tig;
                bhf[j][0] = Bh[wx]; bhf[j][1] = Bh[wx + 4];
                blf[j][0] = Bl[wx]; blf[j][1] = Bl[wx + 4];
            }
            #pragma unroll
            for (int i = 0; i < 4; i++) {
                int wx = (wm*64 + i*16 + gid)*20 + kw + tig;
                uint32_t ah[4] = { Ah[wx], Ah[wx + 160], Ah[wx + 4], Ah[wx + 164] };
                uint32_t al[4] = { Al[wx], Al[wx + 160], Al[wx + 4], Al[wx + 164] };
                #pragma unroll
                for (int j = 0; j < 4; j++) {
                    mma16(acc[i][j], ah, bhf[j]);
                    mma16(acc[i][j], al, bhf[j]);
                    mma16(acc[i][j], ah, blf[j]);
                }
            }
        }
        __syncthreads();
        if (t + 2 < 32) fill(t + 2);
    }

    // epilogue
    #pragma unroll
    for (int i = 0; i < 4; i++) {
        int r0 = m0 + wm*64 + i*16 + gid;
        #pragma unroll
        for (int j = 0; j < 4; j++) {
            int nc = n0 + wn*32 + j*8 + 2*tig;
            float b0 = bias[nc], b1 = bias[nc + 1];
            float v00 = (acc[i][j][0] + b0) * scale;
            float v01 = (acc[i][j][1] + b1) * scale;
            float v10 = (acc[i][j][2] + b0) * scale;
            float v11 = (acc[i][j][3] + b1) * scale;
            if (mode == 0) {
                *(float2*)(outf + (size_t)r0 * GN + nc)       = make_float2(v00, v01);
                *(float2*)(outf + (size_t)(r0 + 8) * GN + nc) = make_float2(v10, v11);
            } else {
                int h = nc >> 6, d = nc & 63;
                int b0i = r0 >> 10, t0 = r0 & (SEQ - 1);
                int b1i = (r0 + 8) >> 10, t1 = (r0 + 8) & (SEQ - 1);
                size_t a0 = ((size_t)((b0i*HEADS + h)*SEQ + t0))*HDIM + d;
                size_t a1 = ((size_t)((b1i*HEADS + h)*SEQ + t1))*HDIM + d;
                bf16 h00 = __float2bfloat16_rn(v00), h01 = __float2bfloat16_rn(v01);
                bf16 h10 = __float2bfloat16_rn(v10), h11 = __float2bfloat16_rn(v11);
                *(uint32_t*)&oh[a0] = pack2(v00, v01);
                *(uint32_t*)&oh[a1] = pack2(v10, v11);
                *(uint32_t*)&ol[a0] = pack2(v00 - __bfloat162float(h00), v01 - __bfloat162float(h01));
                *(uint32_t*)&ol[a1] = pack2(v10 - __bfloat162float(h10), v11 - __bfloat162float(h11));
            }
        }
    }
}

// ---------------- attention kernel: bf16x3 mma S and PV --------------------
#define TQ   32
#define ESTR 1036
// byte offsets in dynamic smem
#define B_E     0
#define B_QH    (TQ*ESTR*4)            // 132608
#define B_QL    (B_QH + TQ*72*2)       // +4608
#define B_KH    (B_QL + TQ*72*2)       // 141824
#define B_KL    (B_KH + 128*72*2)      // +18432 (vT hi tile 64*136*2=17408 fits)
#define B_RWV   (B_KL + 128*72*2)      // 178688
#define B_PROJ  (B_RWV + NB*64*4)      // 187136
#define B_SROW  (B_PROJ + TQ*NB*4)     // 191360
#define B_RPECV (B_SROW + TQ*NB*4)     // 195584
#define ATT_SMEM_BYTES (B_RPECV + TQ*64*4)  // 203776

__device__ __forceinline__ int rpe_clip(int dd) {
    dd = dd < -16 ? -16 : (dd > 16 ? 16 : dd);
    return dd + 16;
}

__global__ __launch_bounds__(512)
void attn_kernel(const float* __restrict__ rpe_w, float* __restrict__ align_out)
{
    extern __shared__ char smc[];
    float*    e     = (float*)smc;
    uint32_t* ew    = (uint32_t*)smc;
    float*    rwv   = (float*)(smc + B_RWV);
    float*    proj  = (float*)(smc + B_PROJ);
    float*    srow  = (float*)(smc + B_SROW);
    float*    rpecv = (float*)(smc + B_RPECV);

    const int bhid = blockIdx.y;
    const int q0   = blockIdx.x * TQ;
    const int tid  = threadIdx.x;
    const int warp = tid >> 5, lane = tid & 31;
    const int gid  = lane >> 2, tig = lane & 3;

    // ---- prologue: load Q hi/lo tile (bf16), rpe_v table ----
    {
        int r = (tid & 255) >> 3, c = tid & 7;
        const bf16* src = (tid < 256) ? g_qhh : g_qhl;
        char* dst = smc + ((tid < 256) ? B_QH : B_QL);
        *(uint4*)(dst + r*144 + c*16) =
            *(const uint4*)&src[((size_t)bhid*SEQ + q0 + r)*HDIM + c*8];
    }
    for (int i = tid; i < NB*64; i += 512) {
        int t = i >> 6, d = i & 63;
        rwv[i] = rpe_w[t*128 + 64 + d];
    }
    __syncthreads();

    // proj[q][t] = qh[q] . rpe_w[t, 0:64]
    {
        const bf16* qh16 = (const bf16*)(smc + B_QH);
        const bf16* ql16 = (const bf16*)(smc + B_QL);
        for (int i = tid; i < TQ*NB; i += 512) {
            int q = i / NB, t = i - q*NB;
            const float* rp = rpe_w + t*128;
            float s = 0.f;
            #pragma unroll 16
            for (int d = 0; d < 64; d++)
                s += (__bfloat162float(qh16[q*72 + d]) + __bfloat162float(ql16[q*72 + d])) * __ldg(&rp[d]);
            proj[i] = s;
        }
    }
    __syncthreads();

    // ---- S = Q K^T (bf16x3 m16n8k16) + rpe_q, into e ----
    const int mS = warp & 1;
    const int np = warp >> 1;
    const uint32_t* QH = (const uint32_t*)(smc + B_QH);
    const uint32_t* QL = (const uint32_t*)(smc + B_QL);
    const uint32_t* KH = (const uint32_t*)(smc + B_KH);
    const uint32_t* KL = (const uint32_t*)(smc + B_KL);

    for (int kt = 0; kt < SEQ; kt += 128) {
        __syncthreads();
        #pragma unroll
        for (int it = 0; it < 4; it++) {
            int idx = tid + it*512;             // 0..2047
            int tile = idx >> 10;
            int r = (idx >> 3) & 127, c = idx & 7;
            const bf16* src = tile ? g_khl : g_khh;
            char* dst = smc + (tile ? B_KL : B_KH);
            *(uint4*)(dst + r*144 + c*16) =
                *(const uint4*)&src[((size_t)bhid*SEQ + kt + r)*HDIM + c*8];
        }
        __syncthreads();

        float acc[2][4] = {{0.f,0.f,0.f,0.f},{0.f,0.f,0.f,0.f}};
        #pragma unroll
        for (int kk = 0; kk < 64; kk += 16) {
            const int kw = kk >> 1;
            int qwx = (mS*16 + gid)*36 + kw + tig;
            uint32_t ah[4] = { QH[qwx], QH[qwx + 288], QH[qwx + 4], QH[qwx + 292] };
            uint32_t al[4] = { QL[qwx], QL[qwx + 288], QL[qwx + 4], QL[qwx + 292] };
            #pragma unroll
            for (int jj = 0; jj < 2; jj++) {
                int wx = (np*16 + jj*8 + gid)*36 + kw + tig;
                uint32_t bh2[2] = { KH[wx], KH[wx + 4] };
                uint32_t bl2[2] = { KL[wx], KL[wx + 4] };
                mma16(acc[jj], ah, bh2);
                mma16(acc[jj], al, bh2);
                mma16(acc[jj], ah, bl2);
            }
        }
        int qA = mS*16 + gid, qB = qA + 8;
        int qgA = q0 + qA, qgB = q0 + qB;
        #pragma unroll
        for (int jj = 0; jj < 2; jj++) {
            int k0c = kt + np*16 + jj*8 + 2*tig;
            e[qA*ESTR + k0c    ] = acc[jj][0] + proj[qA*NB + rpe_clip(qgA - k0c)];
            e[qA*ESTR + k0c + 1] = acc[jj][1] + proj[qA*NB + rpe_clip(qgA - k0c - 1)];
            e[qB*ESTR + k0c    ] = acc[jj][2] + proj[qB*NB + rpe_clip(qgB - k0c)];
            e[qB*ESTR + k0c + 1] = acc[jj][3] + proj[qB*NB + rpe_clip(qgB - k0c - 1)];
        }
    }
    __syncthreads();

    // ---- softmax + alignment out + buckets + pack P to bf16 hi/lo in-place ----
    for (int q = warp*2; q < warp*2 + 2; q++) {
        int qglob = q0 + q;
        float* row = e + q*ESTR;
        float mx = -1e30f;
        #pragma unroll 8
        for (int k = lane; k < SEQ; k += 32) mx = fmaxf(mx, row[k]);
        #pragma unroll
        for (int o = 16; o; o >>= 1) mx = fmaxf(mx, __shfl_xor_sync(0xffffffffu, mx, o));
        float sum = 0.f;
        #pragma unroll 8
        for (int k = lane; k < SEQ; k += 32) {
            float p = __expf(row[k] - mx);
            row[k] = p; sum += p;
        }
        #pragma unroll
        for (int o = 16; o; o >>= 1) sum += __shfl_xor_sync(0xffffffffu, sum, o);
        float inv = 1.f / sum;
        float slo = 0.f, shi = 0.f;
        float* arow = align_out + ((size_t)(bhid * SEQ + qglob)) * SEQ;
        float pv[32];
        #pragma unroll
        for (int i = 0; i < 32; i++) {
            int k = lane + i*32;
            float p = row[k] * inv;
            pv[i] = p; row[k] = p; arow[k] = p;
            if (k <= qglob - 16) slo += p;
            if (k >= qglob + 16) shi += p;
        }
        #pragma unroll
        for (int o = 16; o; o >>= 1) {
            slo += __shfl_xor_sync(0xffffffffu, slo, o);
            shi += __shfl_xor_sync(0xffffffffu, shi, o);
        }
        if (lane == 0) { srow[q*NB + 32] = slo; srow[q*NB + 0] = shi; }
        __syncwarp();
        if (lane >= 1) {
            int k = qglob + 16 - lane;
            srow[q*NB + lane] = (k >= 0 && k < SEQ) ? row[k] : 0.f;
        }
        __syncwarp();
        bf16* hid = (bf16*)row;
        bf16* lod = hid + 1024;
        #pragma unroll
        for (int i = 0; i < 32; i++) {
            int k = lane + i*32;
            bf16 h = __float2bfloat16_rn(pv[i]);
            hid[k] = h;
            lod[k] = __float2bfloat16_rn(pv[i] - __bfloat162float(h));
        }
    }
    __syncthreads();

    // ---- rpecv[32][64] = srow @ rpe_v ----
    for (int i = tid; i < TQ*64; i += 512) {
        int q = i >> 6, d = i & 63;
        float s = 0.f;
        #pragma unroll
        for (int t = 0; t < NB; t++) s += srow[q*NB + t] * rwv[t*64 + d];
        rpecv[i] = s;
    }

    // ---- PV (bf16x3 m16n8k16) over packed P and transposed V ----
    const int mP = warp & 1;
    const int nt = warp >> 1;
    float accP[4] = {0.f, 0.f, 0.f, 0.f};
    for (int kt = 0; kt < SEQ; kt += 128) {
        __syncthreads();
        #pragma unroll
        for (int it = 0; it < 4; it++) {
            int idx = tid + it*512;
            int tile = idx >> 10;
            int r = (idx >> 4) & 63, c = idx & 15;
            const bf16* src = tile ? g_vtl : g_vth;
            char* dst = smc + (tile ? B_KL : B_KH);
            *(uint4*)(dst + r*272 + c*16) =
                *(const uint4*)&src[((size_t)bhid*HDIM + r)*SEQ + kt + c*8];
        }
        __syncthreads();
        const uint32_t* VH = (const uint32_t*)(smc + B_KH);
        const uint32_t* VL = (const uint32_t*)(smc + B_KL);
        #pragma unroll
        for (int kk = 0; kk < 128; kk += 16) {
            const int kwg = (kt + kk) >> 1;
            int ewx = (mP*16 + gid)*ESTR + kwg + tig;
            uint32_t ah[4] = { ew[ewx], ew[ewx + 8*ESTR], ew[ewx + 4], ew[ewx + 8*ESTR + 4] };
            uint32_t al[4] = { ew[ewx + 512], ew[ewx + 8*ESTR + 512],
                               ew[ewx + 516], ew[ewx + 8*ESTR + 516] };
            int wx = (nt*8 + gid)*68 + (kk >> 1) + tig;
            uint32_t bh2[2] = { VH[wx], VH[wx + 4] };
            uint32_t bl2[2] = { VL[wx], VL[wx + 4] };
            mma16(accP, ah, bh2);
            mma16(accP, al, bh2);
            mma16(accP, ah, bl2);
        }
    }

    // ---- epilogue: + rpecv, write ctx as bf16 hi/lo into g_xhi/g_xlo ----
    {
        int qA = mP*16 + gid, qB = qA + 8;
        int d0 = nt*8 + 2*tig;
        int b = bhid >> 4, h = bhid & 15;
        float v00 = accP[0] + rpecv[qA*64 + d0];
        float v01 = accP[1] + rpecv[qA*64 + d0 + 1];
        float v10 = accP[2] + rpecv[qB*64 + d0];
        float v11 = accP[3] + rpecv[qB*64 + d0 + 1];
        size_t a0 = (size_t)(b*SEQ + q0 + qA)*DIMN + h*HDIM + d0;
        size_t a1 = (size_t)(b*SEQ + q0 + qB)*DIMN + h*HDIM + d0;
        bf16 h00 = __float2bfloat16_rn(v00), h01 = __float2bfloat16_rn(v01);
        bf16 h10 = __float2bfloat16_rn(v10), h11 = __float2bfloat16_rn(v11);
        *(uint32_t*)&g_xhi[a0] = pack2(v00, v01);
        *(uint32_t*)&g_xhi[a1] = pack2(v10, v11);
        *(uint32_t*)&g_xlo[a0] = pack2(v00 - __bfloat162float(h00), v01 - __bfloat162float(h01));
        *(uint32_t*)&g_xlo[a1] = pack2(v10 - __bfloat162float(h10), v11 - __bfloat162float(h11));
    }
}

// ---------------- launch ---------------------------------------------------
extern "C" void kernel_launch(void* const* d_in, const int* in_sizes, int n_in,
                              void* d_out, int out_size)
{
    const float* q     = (const float*)d_in[0];
    const float* k     = (const float*)d_in[1];
    const float* v     = (const float*)d_in[2];
    const float* Wq    = (const float*)d_in[3];
    const float* bq    = (const float*)d_in[4];
    const float* Wk    = (const float*)d_in[5];
    const float* bk    = (const float*)d_in[6];
    const float* Wv    = (const float*)d_in[7];
    const float* bv    = (const float*)d_in[8];
    const float* rpe_w = (const float*)d_in[9];
    const float* Wo    = (const float*)d_in[10];
    const float* bo    = (const float*)d_in[11];
    float* outp = (float*)d_out;

    bf16 *xhi, *xlo, *whi, *wlo, *qhh, *qhl, *khh, *khl, *vhh, *vhl, *vth, *vtl;
    cudaGetSymbolAddress((void**)&xhi, g_xhi);
    cudaGetSymbolAddress((void**)&xlo, g_xlo);
    cudaGetSymbolAddress((void**)&whi, g_whi);
    cudaGetSymbolAddress((void**)&wlo, g_wlo);
    cudaGetSymbolAddress((void**)&qhh, g_qhh);
    cudaGetSymbolAddress((void**)&qhl, g_qhl);
    cudaGetSymbolAddress((void**)&khh, g_khh);
    cudaGetSymbolAddress((void**)&khl, g_khl);
    cudaGetSymbolAddress((void**)&vhh, g_vhh);
    cudaGetSymbolAddress((void**)&vhl, g_vhl);
    cudaGetSymbolAddress((void**)&vth, g_vth);
    cudaGetSymbolAddress((void**)&vtl, g_vtl);

    static int inited = 0;
    if (!inited) {
        cudaFuncSetAttribute(gemm_bf16_kernel, cudaFuncAttributeMaxDynamicSharedMemorySize, GEMM_SMEM_BYTES);
        cudaFuncSetAttribute(attn_kernel,      cudaFuncAttributeMaxDynamicSharedMemorySize, ATT_SMEM_BYTES);
        inited = 1;
    }

    dim3 gg(GN/128, GM/128);
    const int xblks = (GM*GK/4)/256, wblks = (GN*GK/4)/256;

    // Q projection (scale 1/sqrt(64) baked in)
    split_bf16_kernel<<<xblks, 256>>>(q,  xhi, xlo, GM*GK/4);
    split_bf16_kernel<<<wblks, 256>>>(Wq, whi, wlo, GN*GK/4);
    gemm_bf16_kernel<<<gg, 256, GEMM_SMEM_BYTES>>>(xhi, xlo, whi, wlo, bq, nullptr, qhh, qhl, 0.125f, 1);
    // K projection
    split_bf16_kernel<<<xblks, 256>>>(k,  xhi, xlo, GM*GK/4);
    split_bf16_kernel<<<wblks, 256>>>(Wk, whi, wlo, GN*GK/4);
    gemm_bf16_kernel<<<gg, 256, GEMM_SMEM_BYTES>>>(xhi, xlo, whi, wlo, bk, nullptr, khh, khl, 1.0f, 1);
    // V projection + transpose
    split_bf16_kernel<<<xblks, 256>>>(v,  xhi, xlo, GM*GK/4);
    split_bf16_kernel<<<wblks, 256>>>(Wv, whi, wlo, GN*GK/4);
    gemm_bf16_kernel<<<gg, 256, GEMM_SMEM_BYTES>>>(xhi, xlo, whi, wlo, bv, nullptr, vhh, vhl, 1.0f, 1);
    vtrans_kernel<<<dim3(SEQ/128, BHN), 256>>>(vhh, vhl, vth, vtl);

    // attention (writes ctx into xhi/xlo)
    float* align_out = outp + (size_t)BATCH * SEQ * DIMN;
    attn_kernel<<<dim3(SEQ/TQ, BHN), 512, ATT_SMEM_BYTES>>>(rpe_w, align_out);

    // output projection
    split_bf16_kernel<<<wblks, 256>>>(Wo, whi, wlo, GN*GK/4);
    gemm_bf16_kernel<<<gg, 256, GEMM_SMEM_BYTES>>>(xhi, xlo, whi, wlo, bo, outp, nullptr, nullptr, 1.0f, 0);
}

// round 6
// speedup vs baseline: 2.5917x; 1.3384x over previous
#include <cuda_runtime.h>
#include <cuda_fp16.h>
#include <cstdint>
#include <cstddef>

#define DIMN   1024
#define HEADS  16
#define HDIM   64
#define BATCH  4
#define SEQ    1024
#define BHN    (BATCH*HEADS)
#define NB     33

#define GM (BATCH*SEQ)
#define GN DIMN
#define GK DIMN

typedef __half h16;

// ---------------- scratch (device globals; no allocation allowed) ----------
__device__ h16 g_xhi[GM*GK];
__device__ h16 g_xlo[GM*GK];
__device__ h16 g_whi[GN*GK];
__device__ h16 g_qhh[BHN*SEQ*HDIM];
__device__ h16 g_qhl[BHN*SEQ*HDIM];
__device__ h16 g_khh[BHN*SEQ*HDIM];
__device__ h16 g_vhh[BHN*SEQ*HDIM];
__device__ h16 g_vth[BHN*HDIM*SEQ];

// ---------------- helpers ---------------------------------------------------
__device__ __forceinline__ void mma16h(float* d, const uint32_t* a, const uint32_t* b) {
    asm volatile(
        "mma.sync.aligned.m16n8k16.row.col.f32.f16.f16.f32 "
        "{%0,%1,%2,%3},{%4,%5,%6,%7},{%8,%9},{%0,%1,%2,%3};"
        : "+f"(d[0]), "+f"(d[1]), "+f"(d[2]), "+f"(d[3])
        : "r"(a[0]), "r"(a[1]), "r"(a[2]), "r"(a[3]), "r"(b[0]), "r"(b[1]));
}
__device__ __forceinline__ void ldsm4(uint32_t* r, uint32_t addr) {
    asm volatile("ldmatrix.sync.aligned.m8n8.x4.shared.b16 {%0,%1,%2,%3}, [%4];"
        : "=r"(r[0]), "=r"(r[1]), "=r"(r[2]), "=r"(r[3]) : "r"(addr));
}
__device__ __forceinline__ void ldsm2(uint32_t* r, uint32_t addr) {
    asm volatile("ldmatrix.sync.aligned.m8n8.x2.shared.b16 {%0,%1}, [%2];"
        : "=r"(r[0]), "=r"(r[1]) : "r"(addr));
}
__device__ __forceinline__ uint32_t smem_u32(const void* p) {
    uint32_t r;
    asm("{ .reg .u64 t; cvta.to.shared.u64 t, %1; cvt.u32.u64 %0, t; }" : "=r"(r) : "l"(p));
    return r;
}
__device__ __forceinline__ uint32_t pack2h(float x, float y) {
    uint32_t r;
    h16 a = __float2half_rn(x), b = __float2half_rn(y);
    asm("mov.b32 %0, {%1, %2};" : "=r"(r) : "h"(*(uint16_t*)&a), "h"(*(uint16_t*)&b));
    return r;
}
#define CP16(dst_u32, src_ptr) \
    asm volatile("cp.async.cg.shared.global [%0], [%1], 16;" :: "r"(dst_u32), "l"(src_ptr))
#define CP_COMMIT() asm volatile("cp.async.commit_group;")
#define CP_WAIT1()  asm volatile("cp.async.wait_group 1;")
#define CP_WAIT0()  asm volatile("cp.async.wait_group 0;")

// ---------------- split fp32 -> fp16 hi/lo ----------------------------------
__global__ __launch_bounds__(256)
void split_x_kernel(const float* __restrict__ src,
                    h16* __restrict__ hi, h16* __restrict__ lo, int n4)
{
    int i = blockIdx.x * 256 + threadIdx.x;
    if (i >= n4) return;
    float4 v = ((const float4*)src)[i];
    float f[4] = {v.x, v.y, v.z, v.w};
    h16 h[4], l[4];
    #pragma unroll
    for (int j = 0; j < 4; j++) {
        h[j] = __float2half_rn(f[j]);
        l[j] = __float2half_rn(f[j] - __half2float(h[j]));
    }
    *(uint2*)&hi[(size_t)i*4] = *(uint2*)h;
    *(uint2*)&lo[(size_t)i*4] = *(uint2*)l;
}
__global__ __launch_bounds__(256)
void conv_w_kernel(const float* __restrict__ src, h16* __restrict__ hi, int n4)
{
    int i = blockIdx.x * 256 + threadIdx.x;
    if (i >= n4) return;
    float4 v = ((const float4*)src)[i];
    h16 h[4] = { __float2half_rn(v.x), __float2half_rn(v.y),
                 __float2half_rn(v.z), __float2half_rn(v.w) };
    *(uint2*)&hi[(size_t)i*4] = *(uint2*)h;
}

// ---------------- V transpose: [bh][t][d] -> [bh][d][t] (hi only) -----------
__global__ __launch_bounds__(256)
void vtrans_kernel(const h16* __restrict__ ih, h16* __restrict__ oh)
{
    __shared__ h16 th[64*136];
    const int bh = blockIdx.y, t0 = blockIdx.x * 128, tid = threadIdx.x;
    #pragma unroll
    for (int it = 0; it < 4; it++) {
        int idx = tid + it*256;
        int r = idx >> 3, c8 = idx & 7;
        h16 a[8];
        *(uint4*)a = *(const uint4*)&ih[((size_t)bh*1024 + t0 + r)*64 + c8*8];
        #pragma unroll
        for (int j = 0; j < 8; j++) th[(c8*8 + j)*136 + r] = a[j];
    }
    __syncthreads();
    #pragma unroll
    for (int it = 0; it < 4; it++) {
        int idx = tid + it*256;
        int d = idx >> 4, tc = idx & 15;
        h16 a[8];
        #pragma unroll
        for (int j = 0; j < 8; j++) a[j] = th[d*136 + tc*8 + j];
        *(uint4*)&oh[((size_t)bh*64 + d)*1024 + t0 + tc*8] = *(uint4*)a;
    }
}

// ---------------- fp16x2 GEMM: C = X @ W^T + bias, *scale -------------------
// M=4096,N=1024,K=1024. 128x128 tile, BK=32, cp.async double-buffered, LDSM.
// mode 0: fp32 out. mode 1: head layout hi+lo. mode 2: head layout hi only.
#define TILEB  (128*80)            // one 128x32-halves tile, 80B rows
#define STAGEB (3*TILEB)           // Ah, Al, Bh
#define GEMM_SMEM_BYTES (2*STAGEB) // 61440

__global__ __launch_bounds__(256, 2)
void gemm_fp16_kernel(const h16* __restrict__ Xh, const h16* __restrict__ Xl,
                      const h16* __restrict__ Wh,
                      const float* __restrict__ bias, float* __restrict__ outf,
                      h16* __restrict__ oh, h16* __restrict__ ol,
                      float scale, int mode)
{
    extern __shared__ char gsm[];
    const uint32_t sb = smem_u32(gsm);
    const int tid  = threadIdx.x;
    const int m0   = blockIdx.y * 128;
    const int n0   = blockIdx.x * 128;
    const int warp = tid >> 5, lane = tid & 31;
    const int gid  = lane >> 2, tig = lane & 3;
    const int wm   = warp >> 2, wn = warp & 3;

    const uint32_t aoffB = (uint32_t)((lane & 15)*80 + ((lane >> 4) << 4));
    const uint32_t boffB = (uint32_t)(((lane & 7) + ((lane >> 4) << 3))*80 + (((lane >> 3) & 1) << 4));

    const h16* srcs[3] = { Xh, Xl, Wh };

    float acc[4][4][4];
    #pragma unroll
    for (int i = 0; i < 4; i++)
        #pragma unroll
        for (int j = 0; j < 4; j++)
            #pragma unroll
            for (int e = 0; e < 4; e++) acc[i][j][e] = 0.f;

    auto fill = [&](int s) {
        const int k0 = s * 32;
        const uint32_t bU = sb + (uint32_t)(s & 1) * STAGEB;
        #pragma unroll
        for (int t = 0; t < 3; t++) {
            const h16* src = srcs[t];
            const int r0 = (t < 2) ? m0 : n0;
            #pragma unroll
            for (int it = 0; it < 2; it++) {
                int idx = tid + it * 256;
                int r = idx >> 2, c = idx & 3;
                CP16(bU + t*TILEB + (uint32_t)(r*80 + c*16),
                     src + (size_t)(r0 + r) * GK + k0 + c*8);
            }
        }
        CP_COMMIT();
    };

    fill(0);
    fill(1);
    for (int t = 0; t < 32; t++) {
        if (t < 31) CP_WAIT1(); else CP_WAIT0();
        __syncthreads();

        const uint32_t st  = sb + (uint32_t)(t & 1) * STAGEB;
        const uint32_t AhU = st;
        const uint32_t AlU = st + TILEB;
        const uint32_t BhU = st + 2*TILEB;

        #pragma unroll
        for (int kkb = 0; kkb < 64; kkb += 32) {   // byte offset of k16 step
            uint32_t bf[2][4];
            ldsm4(bf[0], BhU + (uint32_t)((wn*32     )*80) + boffB + kkb);
            ldsm4(bf[1], BhU + (uint32_t)((wn*32 + 16)*80) + boffB + kkb);
            #pragma unroll
            for (int i = 0; i < 4; i++) {
                uint32_t ah[4], al[4];
                uint32_t rb = (uint32_t)((wm*64 + i*16)*80) + aoffB + kkb;
                ldsm4(ah, AhU + rb);
                ldsm4(al, AlU + rb);
                #pragma unroll
                for (int j = 0; j < 4; j++) {
                    const uint32_t* b = &bf[j >> 1][(j & 1)*2];
                    mma16h(acc[i][j], ah, b);
                    mma16h(acc[i][j], al, b);
                }
            }
        }
        __syncthreads();
        if (t + 2 < 32) fill(t + 2);
    }

    // epilogue
    #pragma unroll
    for (int i = 0; i < 4; i++) {
        int r0 = m0 + wm*64 + i*16 + gid;
        #pragma unroll
        for (int j = 0; j < 4; j++) {
            int nc = n0 + wn*32 + j*8 + 2*tig;
            float b0 = bias[nc], b1 = bias[nc + 1];
            float v00 = (acc[i][j][0] + b0) * scale;
            float v01 = (acc[i][j][1] + b1) * scale;
            float v10 = (acc[i][j][2] + b0) * scale;
            float v11 = (acc[i][j][3] + b1) * scale;
            if (mode == 0) {
                *(float2*)(outf + (size_t)r0 * GN + nc)       = make_float2(v00, v01);
                *(float2*)(outf + (size_t)(r0 + 8) * GN + nc) = make_float2(v10, v11);
            } else {
                int h = nc >> 6, d = nc & 63;
                int b0i = r0 >> 10, t0 = r0 & (SEQ - 1);
                int b1i = (r0 + 8) >> 10, t1 = (r0 + 8) & (SEQ - 1);
                size_t a0 = ((size_t)((b0i*HEADS + h)*SEQ + t0))*HDIM + d;
                size_t a1 = ((size_t)((b1i*HEADS + h)*SEQ + t1))*HDIM + d;
                *(uint32_t*)&oh[a0] = pack2h(v00, v01);
                *(uint32_t*)&oh[a1] = pack2h(v10, v11);
                if (mode == 1) {
                    h16 h00 = __float2half_rn(v00), h01 = __float2half_rn(v01);
                    h16 h10 = __float2half_rn(v10), h11 = __float2half_rn(v11);
                    *(uint32_t*)&ol[a0] = pack2h(v00 - __half2float(h00), v01 - __half2float(h01));
                    *(uint32_t*)&ol[a1] = pack2h(v10 - __half2float(h10), v11 - __half2float(h11));
                }
            }
        }
    }
}

// ---------------- attention kernel ------------------------------------------
#define TQ   32
#define ESTR 1036
// byte offsets in dynamic smem
#define B_E     0
#define B_QH    (TQ*ESTR*4)            // 132608
#define B_QL    (B_QH + TQ*144)        // 137216
#define B_KV    (B_QL + TQ*144)        // 141824  (two 18432B tile buffers)
#define B_RWV   (B_KV + 2*18432)       // 178688
#define B_PROJ  (B_RWV + NB*64*4)      // 187136
#define B_SROW  (B_PROJ + TQ*NB*4)     // 191360
#define B_RPECV (B_SROW + TQ*NB*4)     // 195584
#define ATT_SMEM_BYTES (B_RPECV + TQ*64*4)  // 203776

__device__ __forceinline__ int rpe_clip(int dd) {
    dd = dd < -16 ? -16 : (dd > 16 ? 16 : dd);
    return dd + 16;
}

__global__ __launch_bounds__(512)
void attn_kernel(const float* __restrict__ rpe_w, float* __restrict__ align_out)
{
    extern __shared__ char smc[];
    float* e     = (float*)smc;
    float* rwv   = (float*)(smc + B_RWV);
    float* proj  = (float*)(smc + B_PROJ);
    float* srow  = (float*)(smc + B_SROW);
    float* rpecv = (float*)(smc + B_RPECV);

    const uint32_t sbase = smem_u32(smc);
    const uint32_t sE = sbase, sQH = sbase + B_QH, sQL = sbase + B_QL, sKV = sbase + B_KV;

    const int bhid = blockIdx.y;
    const int q0   = blockIdx.x * TQ;
    const int tid  = threadIdx.x;
    const int warp = tid >> 5, lane = tid & 31;
    const int gid  = lane >> 2, tig = lane & 3;

    // ---- prologue: Q hi/lo tiles, rpe_v table ----
    {
        int r = (tid & 255) >> 3, c = tid & 7;
        const h16* src = (tid < 256) ? g_qhh : g_qhl;
        char* dst = smc + ((tid < 256) ? B_QH : B_QL);
        *(uint4*)(dst + r*144 + c*16) =
            *(const uint4*)&src[((size_t)bhid*SEQ + q0 + r)*HDIM + c*8];
    }
    for (int i = tid; i < NB*64; i += 512) {
        int t = i >> 6, d = i & 63;
        rwv[i] = rpe_w[t*128 + 64 + d];
    }
    __syncthreads();

    // proj[q][t] = qh[q] . rpe_w[t, 0:64]
    {
        const h16* qh16 = (const h16*)(smc + B_QH);
        const h16* ql16 = (const h16*)(smc + B_QL);
        for (int i = tid; i < TQ*NB; i += 512) {
            int q = i / NB, t = i - q*NB;
            const float* rp = rpe_w + t*128;
            float s = 0.f;
            #pragma unroll 16
            for (int d = 0; d < 64; d++)
                s += (__half2float(qh16[q*72 + d]) + __half2float(ql16[q*72 + d])) * __ldg(&rp[d]);
            proj[i] = s;
        }
    }

    // ---- hoist Q fragments (constant across kt) ----
    const int mS = warp & 1;
    const int np = warp >> 1;
    const uint32_t aoffQ = (uint32_t)((lane & 15)*144 + ((lane >> 4) << 4));
    const uint32_t boffS = (uint32_t)(((lane & 7) + ((lane >> 4) << 3))*144 + (((lane >> 3) & 1) << 4));
    uint32_t qhf[4][4], qlf[4][4];
    {
        uint32_t qb = (uint32_t)(mS*16*144) + aoffQ;
        #pragma unroll
        for (int ks = 0; ks < 4; ks++) {
            ldsm4(qhf[ks], sQH + qb + ks*32);
            ldsm4(qlf[ks], sQL + qb + ks*32);
        }
    }

    // ---- S = Q K^T (fp16x2, LDSM) + rpe_q ----
    auto fillK = [&](int ktI) {
        uint32_t bU = sKV + (uint32_t)(ktI & 1)*18432;
        const h16* kb = g_khh + ((size_t)bhid*SEQ + ktI*128)*HDIM;
        #pragma unroll
        for (int it = 0; it < 2; it++) {
            int idx = tid + it*512;
            int r = idx >> 3, c = idx & 7;
            CP16(bU + (uint32_t)(r*144 + c*16), kb + (size_t)r*64 + c*8);
        }
        CP_COMMIT();
    };

    fillK(0);
    for (int ktI = 0; ktI < 8; ktI++) {
        if (ktI < 7) { fillK(ktI + 1); CP_WAIT1(); } else CP_WAIT0();
        __syncthreads();

        uint32_t KU = sKV + (uint32_t)(ktI & 1)*18432 + (uint32_t)(np*16*144);
        float acc[2][4] = {{0.f,0.f,0.f,0.f},{0.f,0.f,0.f,0.f}};
        #pragma unroll
        for (int ks = 0; ks < 4; ks++) {
            uint32_t bf[4];
            ldsm4(bf, KU + boffS + ks*32);
            mma16h(acc[0], qhf[ks], bf);
            mma16h(acc[0], qlf[ks], bf);
            mma16h(acc[1], qhf[ks], bf + 2);
            mma16h(acc[1], qlf[ks], bf + 2);
        }
        int qA = mS*16 + gid, qB = qA + 8;
        int qgA = q0 + qA, qgB = q0 + qB;
        int kt = ktI * 128;
        #pragma unroll
        for (int jj = 0; jj < 2; jj++) {
            int k0c = kt + np*16 + jj*8 + 2*tig;
            e[qA*ESTR + k0c    ] = acc[jj][0] + proj[qA*NB + rpe_clip(qgA - k0c)];
            e[qA*ESTR + k0c + 1] = acc[jj][1] + proj[qA*NB + rpe_clip(qgA - k0c - 1)];
            e[qB*ESTR + k0c    ] = acc[jj][2] + proj[qB*NB + rpe_clip(qgB - k0c)];
            e[qB*ESTR + k0c + 1] = acc[jj][3] + proj[qB*NB + rpe_clip(qgB - k0c - 1)];
        }
        __syncthreads();
    }

    // prefetch V tiles 0,1 (overlaps with softmax)
    auto fillV = [&](int ktI) {
        uint32_t bU = sKV + (uint32_t)(ktI & 1)*18432;
        const h16* vb = g_vth + (size_t)bhid*HDIM*SEQ + ktI*128;
        #pragma unroll
        for (int it = 0; it < 2; it++) {
            int idx = tid + it*512;
            int r = idx >> 4, c = idx & 15;
            CP16(bU + (uint32_t)(r*272 + c*16), vb + (size_t)r*SEQ + c*8);
        }
        CP_COMMIT();
    };
    fillV(0);
    fillV(1);

    // ---- softmax + alignment + buckets + P fp16 pack (vectorized) ----
    for (int q = warp*2; q < warp*2 + 2; q++) {
        int qglob = q0 + q;
        float* row = e + q*ESTR;
        float ev[32];
        float mx = -1e30f;
        #pragma unroll
        for (int i = 0; i < 8; i++) {
            float4 vv = *(float4*)&row[i*128 + lane*4];
            ev[i*4+0] = vv.x; ev[i*4+1] = vv.y; ev[i*4+2] = vv.z; ev[i*4+3] = vv.w;
            mx = fmaxf(mx, fmaxf(fmaxf(vv.x, vv.y), fmaxf(vv.z, vv.w)));
        }
        #pragma unroll
        for (int o = 16; o; o >>= 1) mx = fmaxf(mx, __shfl_xor_sync(0xffffffffu, mx, o));
        float sum = 0.f;
        #pragma unroll
        for (int i = 0; i < 32; i++) { ev[i] = __expf(ev[i] - mx); sum += ev[i]; }
        #pragma unroll
        for (int o = 16; o; o >>= 1) sum += __shfl_xor_sync(0xffffffffu, sum, o);
        float inv = 1.f / sum;

        if (lane) srow[q*NB + lane] = 0.f;
        __syncwarp();

        float slo = 0.f, shi = 0.f;
        h16* hid = (h16*)row;
        h16* lod = hid + 1024;
        float* arow = align_out + ((size_t)(bhid * SEQ + qglob)) * SEQ;
        #pragma unroll
        for (int i = 0; i < 8; i++) {
            int k0 = i*128 + lane*4;
            float p[4];
            #pragma unroll
            for (int c = 0; c < 4; c++) p[c] = ev[i*4 + c] * inv;
            *(float4*)&arow[k0] = make_float4(p[0], p[1], p[2], p[3]);
            h16 ph[4];
            #pragma unroll
            for (int c = 0; c < 4; c++) ph[c] = __float2half_rn(p[c]);
            *(uint2*)&hid[k0] = *(uint2*)ph;
            h16 pl[4];
            #pragma unroll
            for (int c = 0; c < 4; c++) pl[c] = __float2half_rn(p[c] - __half2float(ph[c]));
            *(uint2*)&lod[k0] = *(uint2*)pl;
            #pragma unroll
            for (int c = 0; c < 4; c++) {
                int dd = qglob - (k0 + c);
                if (dd >= 16)       slo += p[c];
                else if (dd <= -16) shi += p[c];
                else                srow[q*NB + dd + 16] = p[c];
            }
        }
        #pragma unroll
        for (int o = 16; o; o >>= 1) {
            slo += __shfl_xor_sync(0xffffffffu, slo, o);
            shi += __shfl_xor_sync(0xffffffffu, shi, o);
        }
        if (lane == 0) { srow[q*NB + 32] = slo; srow[q*NB + 0] = shi; }
    }
    __syncthreads();

    // ---- rpecv[32][64] = srow @ rpe_v ----
    for (int i = tid; i < TQ*64; i += 512) {
        int q = i >> 6, d = i & 63;
        float s = 0.f;
        #pragma unroll
        for (int t = 0; t < NB; t++) s += srow[q*NB + t] * rwv[t*64 + d];
        rpecv[i] = s;
    }

    // ---- PV (fp16x2, LDSM) ----
    const int mP = warp & 1;
    const int nt = warp >> 1;
    const uint32_t aoffP = (uint32_t)((lane & 15)*(ESTR*4) + ((lane >> 4) << 4));
    const uint32_t boffV = (uint32_t)((nt*8 + (lane & 7))*272 + (((lane >> 3) & 1) << 4));
    float accP[4] = {0.f, 0.f, 0.f, 0.f};
    for (int ktI = 0; ktI < 8; ktI++) {
        if (ktI < 7) CP_WAIT1(); else CP_WAIT0();
        __syncthreads();
        uint32_t VU = sKV + (uint32_t)(ktI & 1)*18432;
        uint32_t PB = sE + (uint32_t)(mP*16*(ESTR*4)) + aoffP + (uint32_t)(ktI*256);
        #pragma unroll
        for (int ks = 0; ks < 8; ks++) {
            uint32_t ph[4], pl[4], bv[2];
            ldsm4(ph, PB + ks*32);
            ldsm4(pl, PB + 2048 + ks*32);
            ldsm2(bv, VU + boffV + ks*32);
            mma16h(accP, ph, bv);
            mma16h(accP, pl, bv);
        }
        __syncthreads();
        if (ktI + 2 < 8) fillV(ktI + 2);
    }

    // ---- epilogue: + rpecv, write ctx fp16 hi/lo into g_xhi/g_xlo ----
    {
        int qA = mP*16 + gid, qB = qA + 8;
        int d0 = nt*8 + 2*tig;
        int b = bhid >> 4, h = bhid & 15;
        float v00 = accP[0] + rpecv[qA*64 + d0];
        float v01 = accP[1] + rpecv[qA*64 + d0 + 1];
        float v10 = accP[2] + rpecv[qB*64 + d0];
        float v11 = accP[3] + rpecv[qB*64 + d0 + 1];
        size_t a0 = (size_t)(b*SEQ + q0 + qA)*DIMN + h*HDIM + d0;
        size_t a1 = (size_t)(b*SEQ + q0 + qB)*DIMN + h*HDIM + d0;
        h16 h00 = __float2half_rn(v00), h01 = __float2half_rn(v01);
        h16 h10 = __float2half_rn(v10), h11 = __float2half_rn(v11);
        *(uint32_t*)&g_xhi[a0] = pack2h(v00, v01);
        *(uint32_t*)&g_xhi[a1] = pack2h(v10, v11);
        *(uint32_t*)&g_xlo[a0] = pack2h(v00 - __half2float(h00), v01 - __half2float(h01));
        *(uint32_t*)&g_xlo[a1] = pack2h(v10 - __half2float(h10), v11 - __half2float(h11));
    }
}

// ---------------- launch ---------------------------------------------------
extern "C" void kernel_launch(void* const* d_in, const int* in_sizes, int n_in,
                              void* d_out, int out_size)
{
    const float* q     = (const float*)d_in[0];
    const float* k     = (const float*)d_in[1];
    const float* v     = (const float*)d_in[2];
    const float* Wq    = (const float*)d_in[3];
    const float* bq    = (const float*)d_in[4];
    const float* Wk    = (const float*)d_in[5];
    const float* bk    = (const float*)d_in[6];
    const float* Wv    = (const float*)d_in[7];
    const float* bv    = (const float*)d_in[8];
    const float* rpe_w = (const float*)d_in[9];
    const float* Wo    = (const float*)d_in[10];
    const float* bo    = (const float*)d_in[11];
    float* outp = (float*)d_out;

    h16 *xhi, *xlo, *whi, *qhh, *qhl, *khh, *vhh, *vth;
    cudaGetSymbolAddress((void**)&xhi, g_xhi);
    cudaGetSymbolAddress((void**)&xlo, g_xlo);
    cudaGetSymbolAddress((void**)&whi, g_whi);
    cudaGetSymbolAddress((void**)&qhh, g_qhh);
    cudaGetSymbolAddress((void**)&qhl, g_qhl);
    cudaGetSymbolAddress((void**)&khh, g_khh);
    cudaGetSymbolAddress((void**)&vhh, g_vhh);
    cudaGetSymbolAddress((void**)&vth, g_vth);

    static int inited = 0;
    if (!inited) {
        cudaFuncSetAttribute(gemm_fp16_kernel, cudaFuncAttributeMaxDynamicSharedMemorySize, GEMM_SMEM_BYTES);
        cudaFuncSetAttribute(attn_kernel,      cudaFuncAttributeMaxDynamicSharedMemorySize, ATT_SMEM_BYTES);
        inited = 1;
    }

    dim3 gg(GN/128, GM/128);
    const int xblks = (GM*GK/4)/256, wblks = (GN*GK/4)/256;

    // Q projection (1/sqrt(64) baked in): hi+lo out
    split_x_kernel<<<xblks, 256>>>(q, xhi, xlo, GM*GK/4);
    conv_w_kernel<<<wblks, 256>>>(Wq, whi, GN*GK/4);
    gemm_fp16_kernel<<<gg, 256, GEMM_SMEM_BYTES>>>(xhi, xlo, whi, bq, nullptr, qhh, qhl, 0.125f, 1);
    // K projection: hi only
    split_x_kernel<<<xblks, 256>>>(k, xhi, xlo, GM*GK/4);
    conv_w_kernel<<<wblks, 256>>>(Wk, whi, GN*GK/4);
    gemm_fp16_kernel<<<gg, 256, GEMM_SMEM_BYTES>>>(xhi, xlo, whi, bk, nullptr, khh, nullptr, 1.0f, 2);
    // V projection: hi only, then transpose
    split_x_kernel<<<xblks, 256>>>(v, xhi, xlo, GM*GK/4);
    conv_w_kernel<<<wblks, 256>>>(Wv, whi, GN*GK/4);
    gemm_fp16_kernel<<<gg, 256, GEMM_SMEM_BYTES>>>(xhi, xlo, whi, bv, nullptr, vhh, nullptr, 1.0f, 2);
    vtrans_kernel<<<dim3(SEQ/128, BHN), 256>>>(vhh, vth);

    // attention (writes ctx into xhi/xlo)
    float* align_out = outp + (size_t)BATCH * SEQ * DIMN;
    attn_kernel<<<dim3(SEQ/TQ, BHN), 512, ATT_SMEM_BYTES>>>(rpe_w, align_out);

    // output projection
    conv_w_kernel<<<wblks, 256>>>(Wo, whi, GN*GK/4);
    gemm_fp16_kernel<<<gg, 256, GEMM_SMEM_BYTES>>>(xhi, xlo, whi, bo, outp, nullptr, nullptr, 1.0f, 0);
}

// round 7
// speedup vs baseline: 2.5928x; 1.0004x over previous
#include <cuda_runtime.h>
#include <cuda_fp16.h>
#include <cstdint>
#include <cstddef>

#define DIMN   1024
#define HEADS  16
#define HDIM   64
#define BATCH  4
#define SEQ    1024
#define BHN    (BATCH*HEADS)
#define NB     33

#define GM (BATCH*SEQ)
#define GN DIMN
#define GK DIMN

typedef __half h16;

// ---------------- scratch (device globals; no allocation allowed) ----------
__device__ h16 g_xhi[GM*GK];
__device__ h16 g_xlo[GM*GK];
__device__ h16 g_whi[GN*GK];
__device__ h16 g_qhh[BHN*SEQ*HDIM];
__device__ h16 g_qhl[BHN*SEQ*HDIM];
__device__ h16 g_khh[BHN*SEQ*HDIM];
__device__ h16 g_vhh[BHN*SEQ*HDIM];
__device__ h16 g_vth[BHN*HDIM*SEQ];

// ---------------- helpers ---------------------------------------------------
__device__ __forceinline__ void mma16h(float* d, const uint32_t* a, const uint32_t* b) {
    asm volatile(
        "mma.sync.aligned.m16n8k16.row.col.f32.f16.f16.f32 "
        "{%0,%1,%2,%3},{%4,%5,%6,%7},{%8,%9},{%0,%1,%2,%3};"
        : "+f"(d[0]), "+f"(d[1]), "+f"(d[2]), "+f"(d[3])
        : "r"(a[0]), "r"(a[1]), "r"(a[2]), "r"(a[3]), "r"(b[0]), "r"(b[1]));
}
__device__ __forceinline__ void ldsm4(uint32_t* r, uint32_t addr) {
    asm volatile("ldmatrix.sync.aligned.m8n8.x4.shared.b16 {%0,%1,%2,%3}, [%4];"
        : "=r"(r[0]), "=r"(r[1]), "=r"(r[2]), "=r"(r[3]) : "r"(addr));
}
__device__ __forceinline__ void ldsm2(uint32_t* r, uint32_t addr) {
    asm volatile("ldmatrix.sync.aligned.m8n8.x2.shared.b16 {%0,%1}, [%2];"
        : "=r"(r[0]), "=r"(r[1]) : "r"(addr));
}
__device__ __forceinline__ uint32_t smem_u32(const void* p) {
    uint32_t r;
    asm("{ .reg .u64 t; cvta.to.shared.u64 t, %1; cvt.u32.u64 %0, t; }" : "=r"(r) : "l"(p));
    return r;
}
__device__ __forceinline__ uint32_t pack2h(float x, float y) {
    uint32_t r;
    h16 a = __float2half_rn(x), b = __float2half_rn(y);
    asm("mov.b32 %0, {%1, %2};" : "=r"(r) : "h"(*(uint16_t*)&a), "h"(*(uint16_t*)&b));
    return r;
}
#define CP16(dst_u32, src_ptr) \
    asm volatile("cp.async.cg.shared.global [%0], [%1], 16;" :: "r"(dst_u32), "l"(src_ptr))
#define CP_COMMIT() asm volatile("cp.async.commit_group;")
#define CP_WAIT1()  asm volatile("cp.async.wait_group 1;")
#define CP_WAIT0()  asm volatile("cp.async.wait_group 0;")

// ---------------- split fp32 -> fp16 hi/lo ----------------------------------
__global__ __launch_bounds__(256)
void split_x_kernel(const float* __restrict__ src,
                    h16* __restrict__ hi, h16* __restrict__ lo, int n4)
{
    int i = blockIdx.x * 256 + threadIdx.x;
    if (i >= n4) return;
    float4 v = ((const float4*)src)[i];
    float f[4] = {v.x, v.y, v.z, v.w};
    h16 h[4], l[4];
    #pragma unroll
    for (int j = 0; j < 4; j++) {
        h[j] = __float2half_rn(f[j]);
        l[j] = __float2half_rn(f[j] - __half2float(h[j]));
    }
    *(uint2*)&hi[(size_t)i*4] = *(uint2*)h;
    *(uint2*)&lo[(size_t)i*4] = *(uint2*)l;
}
__global__ __launch_bounds__(256)
void conv_w_kernel(const float* __restrict__ src, h16* __restrict__ hi, int n4)
{
    int i = blockIdx.x * 256 + threadIdx.x;
    if (i >= n4) return;
    float4 v = ((const float4*)src)[i];
    h16 h[4] = { __float2half_rn(v.x), __float2half_rn(v.y),
                 __float2half_rn(v.z), __float2half_rn(v.w) };
    *(uint2*)&hi[(size_t)i*4] = *(uint2*)h;
}

// ---------------- V transpose: [bh][t][d] -> [bh][d][t] (hi only) -----------
__global__ __launch_bounds__(256)
void vtrans_kernel(const h16* __restrict__ ih, h16* __restrict__ oh)
{
    __shared__ h16 th[64*136];
    const int bh = blockIdx.y, t0 = blockIdx.x * 128, tid = threadIdx.x;
    #pragma unroll
    for (int it = 0; it < 4; it++) {
        int idx = tid + it*256;
        int r = idx >> 3, c8 = idx & 7;
        h16 a[8];
        *(uint4*)a = *(const uint4*)&ih[((size_t)bh*1024 + t0 + r)*64 + c8*8];
        #pragma unroll
        for (int j = 0; j < 8; j++) th[(c8*8 + j)*136 + r] = a[j];
    }
    __syncthreads();
    #pragma unroll
    for (int it = 0; it < 4; it++) {
        int idx = tid + it*256;
        int d = idx >> 4, tc = idx & 15;
        h16 a[8];
        #pragma unroll
        for (int j = 0; j < 8; j++) a[j] = th[d*136 + tc*8 + j];
        *(uint4*)&oh[((size_t)bh*64 + d)*1024 + t0 + tc*8] = *(uint4*)a;
    }
}

// ---------------- fp16x2 GEMM: C = X @ W^T + bias, *scale -------------------
// M=4096,N=1024,K=1024. 128x128 tile, BK=32, cp.async double-buffered, LDSM.
// mode 0: fp32 out. mode 1: head layout hi+lo. mode 2: head layout hi only.
#define TILEB  (128*80)            // one 128x32-halves tile, 80B rows
#define STAGEB (3*TILEB)           // Ah, Al, Bh
#define GEMM_SMEM_BYTES (2*STAGEB) // 61440

__global__ __launch_bounds__(256, 2)
void gemm_fp16_kernel(const h16* __restrict__ Xh, const h16* __restrict__ Xl,
                      const h16* __restrict__ Wh,
                      const float* __restrict__ bias, float* __restrict__ outf,
                      h16* __restrict__ oh, h16* __restrict__ ol,
                      float scale, int mode)
{
    extern __shared__ char gsm[];
    const uint32_t sb = smem_u32(gsm);
    const int tid  = threadIdx.x;
    const int m0   = blockIdx.y * 128;
    const int n0   = blockIdx.x * 128;
    const int warp = tid >> 5, lane = tid & 31;
    const int gid  = lane >> 2, tig = lane & 3;
    const int wm   = warp >> 2, wn = warp & 3;

    const uint32_t aoffB = (uint32_t)((lane & 15)*80 + ((lane >> 4) << 4));
    const uint32_t boffB = (uint32_t)(((lane & 7) + ((lane >> 4) << 3))*80 + (((lane >> 3) & 1) << 4));

    const h16* srcs[3] = { Xh, Xl, Wh };

    float acc[4][4][4];
    #pragma unroll
    for (int i = 0; i < 4; i++)
        #pragma unroll
        for (int j = 0; j < 4; j++)
            #pragma unroll
            for (int e = 0; e < 4; e++) acc[i][j][e] = 0.f;

    auto fill = [&](int s) {
        const int k0 = s * 32;
        const uint32_t bU = sb + (uint32_t)(s & 1) * STAGEB;
        #pragma unroll
        for (int t = 0; t < 3; t++) {
            const h16* src = srcs[t];
            const int r0 = (t < 2) ? m0 : n0;
            #pragma unroll
            for (int it = 0; it < 2; it++) {
                int idx = tid + it * 256;
                int r = idx >> 2, c = idx & 3;
                CP16(bU + t*TILEB + (uint32_t)(r*80 + c*16),
                     src + (size_t)(r0 + r) * GK + k0 + c*8);
            }
        }
        CP_COMMIT();
    };

    fill(0);
    fill(1);
    for (int t = 0; t < 32; t++) {
        if (t < 31) CP_WAIT1(); else CP_WAIT0();
        __syncthreads();

        const uint32_t st  = sb + (uint32_t)(t & 1) * STAGEB;
        const uint32_t AhU = st;
        const uint32_t AlU = st + TILEB;
        const uint32_t BhU = st + 2*TILEB;

        #pragma unroll
        for (int kkb = 0; kkb < 64; kkb += 32) {   // byte offset of k16 step
            uint32_t bf[2][4];
            ldsm4(bf[0], BhU + (uint32_t)((wn*32     )*80) + boffB + kkb);
            ldsm4(bf[1], BhU + (uint32_t)((wn*32 + 16)*80) + boffB + kkb);
            #pragma unroll
            for (int i = 0; i < 4; i++) {
                uint32_t ah[4], al[4];
                uint32_t rb = (uint32_t)((wm*64 + i*16)*80) + aoffB + kkb;
                ldsm4(ah, AhU + rb);
                ldsm4(al, AlU + rb);
                #pragma unroll
                for (int j = 0; j < 4; j++) {
                    const uint32_t* b = &bf[j >> 1][(j & 1)*2];
                    mma16h(acc[i][j], ah, b);
                    mma16h(acc[i][j], al, b);
                }
            }
        }
        __syncthreads();
        if (t + 2 < 32) fill(t + 2);
    }

    // epilogue
    #pragma unroll
    for (int i = 0; i < 4; i++) {
        int r0 = m0 + wm*64 + i*16 + gid;
        #pragma unroll
        for (int j = 0; j < 4; j++) {
            int nc = n0 + wn*32 + j*8 + 2*tig;
            float b0 = bias[nc], b1 = bias[nc + 1];
            float v00 = (acc[i][j][0] + b0) * scale;
            float v01 = (acc[i][j][1] + b1) * scale;
            float v10 = (acc[i][j][2] + b0) * scale;
            float v11 = (acc[i][j][3] + b1) * scale;
            if (mode == 0) {
                *(float2*)(outf + (size_t)r0 * GN + nc)       = make_float2(v00, v01);
                *(float2*)(outf + (size_t)(r0 + 8) * GN + nc) = make_float2(v10, v11);
            } else {
                int h = nc >> 6, d = nc & 63;
                int b0i = r0 >> 10, t0 = r0 & (SEQ - 1);
                int b1i = (r0 + 8) >> 10, t1 = (r0 + 8) & (SEQ - 1);
                size_t a0 = ((size_t)((b0i*HEADS + h)*SEQ + t0))*HDIM + d;
                size_t a1 = ((size_t)((b1i*HEADS + h)*SEQ + t1))*HDIM + d;
                *(uint32_t*)&oh[a0] = pack2h(v00, v01);
                *(uint32_t*)&oh[a1] = pack2h(v10, v11);
                if (mode == 1) {
                    h16 h00 = __float2half_rn(v00), h01 = __float2half_rn(v01);
                    h16 h10 = __float2half_rn(v10), h11 = __float2half_rn(v11);
                    *(uint32_t*)&ol[a0] = pack2h(v00 - __half2float(h00), v01 - __half2float(h01));
                    *(uint32_t*)&ol[a1] = pack2h(v10 - __half2float(h10), v11 - __half2float(h11));
                }
            }
        }
    }
}

// ---------------- attention kernel ------------------------------------------
#define TQ   32
#define ESTR 1036
// byte offsets in dynamic smem
#define B_E     0
#define B_QH    (TQ*ESTR*4)            // 132608
#define B_QL    (B_QH + TQ*144)        // 137216
#define B_KV    (B_QL + TQ*144)        // 141824  (two 18432B tile buffers)
#define B_RWV   (B_KV + 2*18432)       // 178688
#define B_PROJ  (B_RWV + NB*64*4)      // 187136
#define B_SROW  (B_PROJ + TQ*NB*4)     // 191360
#define B_RPECV (B_SROW + TQ*NB*4)     // 195584
#define ATT_SMEM_BYTES (B_RPECV + TQ*64*4)  // 203776

__device__ __forceinline__ int rpe_clip(int dd) {
    dd = dd < -16 ? -16 : (dd > 16 ? 16 : dd);
    return dd + 16;
}

__global__ __launch_bounds__(512)
void attn_kernel(const float* __restrict__ rpe_w, float* __restrict__ align_out)
{
    extern __shared__ char smc[];
    float* e     = (float*)smc;
    float* rwv   = (float*)(smc + B_RWV);
    float* proj  = (float*)(smc + B_PROJ);
    float* srow  = (float*)(smc + B_SROW);
    float* rpecv = (float*)(smc + B_RPECV);

    const uint32_t sbase = smem_u32(smc);
    const uint32_t sE = sbase, sQH = sbase + B_QH, sQL = sbase + B_QL, sKV = sbase + B_KV;

    const int bhid = blockIdx.y;
    const int q0   = blockIdx.x * TQ;
    const int tid  = threadIdx.x;
    const int warp = tid >> 5, lane = tid & 31;
    const int gid  = lane >> 2, tig = lane & 3;

    // ---- prologue: Q hi/lo tiles, rpe_v table ----
    {
        int r = (tid & 255) >> 3, c = tid & 7;
        const h16* src = (tid < 256) ? g_qhh : g_qhl;
        char* dst = smc + ((tid < 256) ? B_QH : B_QL);
        *(uint4*)(dst + r*144 + c*16) =
            *(const uint4*)&src[((size_t)bhid*SEQ + q0 + r)*HDIM + c*8];
    }
    for (int i = tid; i < NB*64; i += 512) {
        int t = i >> 6, d = i & 63;
        rwv[i] = rpe_w[t*128 + 64 + d];
    }
    __syncthreads();

    // proj[q][t] = qh[q] . rpe_w[t, 0:64]
    {
        const h16* qh16 = (const h16*)(smc + B_QH);
        const h16* ql16 = (const h16*)(smc + B_QL);
        for (int i = tid; i < TQ*NB; i += 512) {
            int q = i / NB, t = i - q*NB;
            const float* rp = rpe_w + t*128;
            float s = 0.f;
            #pragma unroll 16
            for (int d = 0; d < 64; d++)
                s += (__half2float(qh16[q*72 + d]) + __half2float(ql16[q*72 + d])) * __ldg(&rp[d]);
            proj[i] = s;
        }
    }

    // ---- hoist Q fragments (constant across kt) ----
    const int mS = warp & 1;
    const int np = warp >> 1;
    const uint32_t aoffQ = (uint32_t)((lane & 15)*144 + ((lane >> 4) << 4));
    const uint32_t boffS = (uint32_t)(((lane & 7) + ((lane >> 4) << 3))*144 + (((lane >> 3) & 1) << 4));
    uint32_t qhf[4][4], qlf[4][4];
    {
        uint32_t qb = (uint32_t)(mS*16*144) + aoffQ;
        #pragma unroll
        for (int ks = 0; ks < 4; ks++) {
            ldsm4(qhf[ks], sQH + qb + ks*32);
            ldsm4(qlf[ks], sQL + qb + ks*32);
        }
    }

    // ---- S = Q K^T (fp16x2, LDSM) + rpe_q ----
    auto fillK = [&](int ktI) {
        uint32_t bU = sKV + (uint32_t)(ktI & 1)*18432;
        const h16* kb = g_khh + ((size_t)bhid*SEQ + ktI*128)*HDIM;
        #pragma unroll
        for (int it = 0; it < 2; it++) {
            int idx = tid + it*512;
            int r = idx >> 3, c = idx & 7;
            CP16(bU + (uint32_t)(r*144 + c*16), kb + (size_t)r*64 + c*8);
        }
        CP_COMMIT();
    };

    fillK(0);
    for (int ktI = 0; ktI < 8; ktI++) {
        if (ktI < 7) { fillK(ktI + 1); CP_WAIT1(); } else CP_WAIT0();
        __syncthreads();

        uint32_t KU = sKV + (uint32_t)(ktI & 1)*18432 + (uint32_t)(np*16*144);
        float acc[2][4] = {{0.f,0.f,0.f,0.f},{0.f,0.f,0.f,0.f}};
        #pragma unroll
        for (int ks = 0; ks < 4; ks++) {
            uint32_t bf[4];
            ldsm4(bf, KU + boffS + ks*32);
            mma16h(acc[0], qhf[ks], bf);
            mma16h(acc[0], qlf[ks], bf);
            mma16h(acc[1], qhf[ks], bf + 2);
            mma16h(acc[1], qlf[ks], bf + 2);
        }
        int qA = mS*16 + gid, qB = qA + 8;
        int qgA = q0 + qA, qgB = q0 + qB;
        int kt = ktI * 128;
        #pragma unroll
        for (int jj = 0; jj < 2; jj++) {
            int k0c = kt + np*16 + jj*8 + 2*tig;
            e[qA*ESTR + k0c    ] = acc[jj][0] + proj[qA*NB + rpe_clip(qgA - k0c)];
            e[qA*ESTR + k0c + 1] = acc[jj][1] + proj[qA*NB + rpe_clip(qgA - k0c - 1)];
            e[qB*ESTR + k0c    ] = acc[jj][2] + proj[qB*NB + rpe_clip(qgB - k0c)];
            e[qB*ESTR + k0c + 1] = acc[jj][3] + proj[qB*NB + rpe_clip(qgB - k0c - 1)];
        }
        __syncthreads();
    }

    // prefetch V tiles 0,1 (overlaps with softmax)
    auto fillV = [&](int ktI) {
        uint32_t bU = sKV + (uint32_t)(ktI & 1)*18432;
        const h16* vb = g_vth + (size_t)bhid*HDIM*SEQ + ktI*128;
        #pragma unroll
        for (int it = 0; it < 2; it++) {
            int idx = tid + it*512;
            int r = idx >> 4, c = idx & 15;
            CP16(bU + (uint32_t)(r*272 + c*16), vb + (size_t)r*SEQ + c*8);
        }
        CP_COMMIT();
    };
    fillV(0);
    fillV(1);

    // ---- softmax + alignment + buckets + P fp16 pack (vectorized) ----
    for (int q = warp*2; q < warp*2 + 2; q++) {
        int qglob = q0 + q;
        float* row = e + q*ESTR;
        float ev[32];
        float mx = -1e30f;
        #pragma unroll
        for (int i = 0; i < 8; i++) {
            float4 vv = *(float4*)&row[i*128 + lane*4];
            ev[i*4+0] = vv.x; ev[i*4+1] = vv.y; ev[i*4+2] = vv.z; ev[i*4+3] = vv.w;
            mx = fmaxf(mx, fmaxf(fmaxf(vv.x, vv.y), fmaxf(vv.z, vv.w)));
        }
        #pragma unroll
        for (int o = 16; o; o >>= 1) mx = fmaxf(mx, __shfl_xor_sync(0xffffffffu, mx, o));
        float sum = 0.f;
        #pragma unroll
        for (int i = 0; i < 32; i++) { ev[i] = __expf(ev[i] - mx); sum += ev[i]; }
        #pragma unroll
        for (int o = 16; o; o >>= 1) sum += __shfl_xor_sync(0xffffffffu, sum, o);
        float inv = 1.f / sum;

        if (lane) srow[q*NB + lane] = 0.f;
        __syncwarp();

        float slo = 0.f, shi = 0.f;
        h16* hid = (h16*)row;
        h16* lod = hid + 1024;
        float* arow = align_out + ((size_t)(bhid * SEQ + qglob)) * SEQ;
        #pragma unroll
        for (int i = 0; i < 8; i++) {
            int k0 = i*128 + lane*4;
            float p[4];
            #pragma unroll
            for (int c = 0; c < 4; c++) p[c] = ev[i*4 + c] * inv;
            *(float4*)&arow[k0] = make_float4(p[0], p[1], p[2], p[3]);
            h16 ph[4];
            #pragma unroll
            for (int c = 0; c < 4; c++) ph[c] = __float2half_rn(p[c]);
            *(uint2*)&hid[k0] = *(uint2*)ph;
            h16 pl[4];
            #pragma unroll
            for (int c = 0; c < 4; c++) pl[c] = __float2half_rn(p[c] - __half2float(ph[c]));
            *(uint2*)&lod[k0] = *(uint2*)pl;
            #pragma unroll
            for (int c = 0; c < 4; c++) {
                int dd = qglob - (k0 + c);
                if (dd >= 16)       slo += p[c];
                else if (dd <= -16) shi += p[c];
                else                srow[q*NB + dd + 16] = p[c];
            }
        }
        #pragma unroll
        for (int o = 16; o; o >>= 1) {
            slo += __shfl_xor_sync(0xffffffffu, slo, o);
            shi += __shfl_xor_sync(0xffffffffu, shi, o);
        }
        if (lane == 0) { srow[q*NB + 32] = slo; srow[q*NB + 0] = shi; }
    }
    __syncthreads();

    // ---- rpecv[32][64] = srow @ rpe_v ----
    for (int i = tid; i < TQ*64; i += 512) {
        int q = i >> 6, d = i & 63;
        float s = 0.f;
        #pragma unroll
        for (int t = 0; t < NB; t++) s += srow[q*NB + t] * rwv[t*64 + d];
        rpecv[i] = s;
    }

    // ---- PV (fp16x2, LDSM) ----
    const int mP = warp & 1;
    const int nt = warp >> 1;
    const uint32_t aoffP = (uint32_t)((lane & 15)*(ESTR*4) + ((lane >> 4) << 4));
    const uint32_t boffV = (uint32_t)((nt*8 + (lane & 7))*272 + (((lane >> 3) & 1) << 4));
    float accP[4] = {0.f, 0.f, 0.f, 0.f};
    for (int ktI = 0; ktI < 8; ktI++) {
        if (ktI < 7) CP_WAIT1(); else CP_WAIT0();
        __syncthreads();
        uint32_t VU = sKV + (uint32_t)(ktI & 1)*18432;
        uint32_t PB = sE + (uint32_t)(mP*16*(ESTR*4)) + aoffP + (uint32_t)(ktI*256);
        #pragma unroll
        for (int ks = 0; ks < 8; ks++) {
            uint32_t ph[4], pl[4], bv[2];
            ldsm4(ph, PB + ks*32);
            ldsm4(pl, PB + 2048 + ks*32);
            ldsm2(bv, VU + boffV + ks*32);
            mma16h(accP, ph, bv);
            mma16h(accP, pl, bv);
        }
        __syncthreads();
        if (ktI + 2 < 8) fillV(ktI + 2);
    }

    // ---- epilogue: + rpecv, write ctx fp16 hi/lo into g_xhi/g_xlo ----
    {
        int qA = mP*16 + gid, qB = qA + 8;
        int d0 = nt*8 + 2*tig;
        int b = bhid >> 4, h = bhid & 15;
        float v00 = accP[0] + rpecv[qA*64 + d0];
        float v01 = accP[1] + rpecv[qA*64 + d0 + 1];
        float v10 = accP[2] + rpecv[qB*64 + d0];
        float v11 = accP[3] + rpecv[qB*64 + d0 + 1];
        size_t a0 = (size_t)(b*SEQ + q0 + qA)*DIMN + h*HDIM + d0;
        size_t a1 = (size_t)(b*SEQ + q0 + qB)*DIMN + h*HDIM + d0;
        h16 h00 = __float2half_rn(v00), h01 = __float2half_rn(v01);
        h16 h10 = __float2half_rn(v10), h11 = __float2half_rn(v11);
        *(uint32_t*)&g_xhi[a0] = pack2h(v00, v01);
        *(uint32_t*)&g_xhi[a1] = pack2h(v10, v11);
        *(uint32_t*)&g_xlo[a0] = pack2h(v00 - __half2float(h00), v01 - __half2float(h01));
        *(uint32_t*)&g_xlo[a1] = pack2h(v10 - __half2float(h10), v11 - __half2float(h11));
    }
}

// ---------------- launch ---------------------------------------------------
extern "C" void kernel_launch(void* const* d_in, const int* in_sizes, int n_in,
                              void* d_out, int out_size)
{
    const float* q     = (const float*)d_in[0];
    const float* k     = (const float*)d_in[1];
    const float* v     = (const float*)d_in[2];
    const float* Wq    = (const float*)d_in[3];
    const float* bq    = (const float*)d_in[4];
    const float* Wk    = (const float*)d_in[5];
    const float* bk    = (const float*)d_in[6];
    const float* Wv    = (const float*)d_in[7];
    const float* bv    = (const float*)d_in[8];
    const float* rpe_w = (const float*)d_in[9];
    const float* Wo    = (const float*)d_in[10];
    const float* bo    = (const float*)d_in[11];
    float* outp = (float*)d_out;

    h16 *xhi, *xlo, *whi, *qhh, *qhl, *khh, *vhh, *vth;
    cudaGetSymbolAddress((void**)&xhi, g_xhi);
    cudaGetSymbolAddress((void**)&xlo, g_xlo);
    cudaGetSymbolAddress((void**)&whi, g_whi);
    cudaGetSymbolAddress((void**)&qhh, g_qhh);
    cudaGetSymbolAddress((void**)&qhl, g_qhl);
    cudaGetSymbolAddress((void**)&khh, g_khh);
    cudaGetSymbolAddress((void**)&vhh, g_vhh);
    cudaGetSymbolAddress((void**)&vth, g_vth);

    static int inited = 0;
    if (!inited) {
        cudaFuncSetAttribute(gemm_fp16_kernel, cudaFuncAttributeMaxDynamicSharedMemorySize, GEMM_SMEM_BYTES);
        cudaFuncSetAttribute(attn_kernel,      cudaFuncAttributeMaxDynamicSharedMemorySize, ATT_SMEM_BYTES);
        inited = 1;
    }

    dim3 gg(GN/128, GM/128);
    const int xblks = (GM*GK/4)/256, wblks = (GN*GK/4)/256;

    // Q projection (1/sqrt(64) baked in): hi+lo out
    split_x_kernel<<<xblks, 256>>>(q, xhi, xlo, GM*GK/4);
    conv_w_kernel<<<wblks, 256>>>(Wq, whi, GN*GK/4);
    gemm_fp16_kernel<<<gg, 256, GEMM_SMEM_BYTES>>>(xhi, xlo, whi, bq, nullptr, qhh, qhl, 0.125f, 1);
    // K projection: hi only
    split_x_kernel<<<xblks, 256>>>(k, xhi, xlo, GM*GK/4);
    conv_w_kernel<<<wblks, 256>>>(Wk, whi, GN*GK/4);
    gemm_fp16_kernel<<<gg, 256, GEMM_SMEM_BYTES>>>(xhi, xlo, whi, bk, nullptr, khh, nullptr, 1.0f, 2);
    // V projection: hi only, then transpose
    split_x_kernel<<<xblks, 256>>>(v, xhi, xlo, GM*GK/4);
    conv_w_kernel<<<wblks, 256>>>(Wv, whi, GN*GK/4);
    gemm_fp16_kernel<<<gg, 256, GEMM_SMEM_BYTES>>>(xhi, xlo, whi, bv, nullptr, vhh, nullptr, 1.0f, 2);
    vtrans_kernel<<<dim3(SEQ/128, BHN), 256>>>(vhh, vth);

    // attention (writes ctx into xhi/xlo)
    float* align_out = outp + (size_t)BATCH * SEQ * DIMN;
    attn_kernel<<<dim3(SEQ/TQ, BHN), 512, ATT_SMEM_BYTES>>>(rpe_w, align_out);

    // output projection
    conv_w_kernel<<<wblks, 256>>>(Wo, whi, GN*GK/4);
    gemm_fp16_kernel<<<gg, 256, GEMM_SMEM_BYTES>>>(xhi, xlo, whi, bo, outp, nullptr, nullptr, 1.0f, 0);
}